// round 10
// baseline (speedup 1.0000x reference)
#include <cuda_runtime.h>
#include <cuda_fp16.h>

// ---------------------------------------------------------------------------
// Inverse DTCWT, 3 levels, FUSED col+row per level. fp16 intermediates.
// Phase 1 (column filter) items are split into y1-items and y2-items so all
// 256 threads work; results land in fp16 smem tiles with reflection halo
// baked in; phase 2 (row filter) is branch-free out of smem.
// Window map (around 2n): [0]=-4 [1]=-2 [2]=0 [3]=+2 [4]=-1 [5]=+1 [6]=+3 [7]=+5
// ---------------------------------------------------------------------------

#define SH   0.70710678118654752440f
#define C_A  0.23389032f
#define C_B  0.5875183f
#define C_C  0.11430184f
#define C_D  0.76027237f
#define C_E  0.08832942f
#define C_F  0.03516384f

#define G0   0.35355339059327f
#define G1   0.70710678118655f
#define Q_E  (-0.08838834764832f)
#define Q_D  (-0.17677669529664f)
#define Q_F  0.53033008588991f

#define LP0(L) ( C_A*L[1] + C_B*L[2] - C_C*L[3])
#define LP1(L) ( C_D*L[5] - C_E*L[6] + C_F*L[7])
#define LP2(L) ( C_F*L[0] - C_E*L[1] + C_D*L[2])
#define LP3(L) (-C_C*L[4] + C_B*L[5] + C_A*L[6])
#define HP0(H) (-C_D*H[5] + C_E*H[6] - C_F*H[7])
#define HP1(H) ( C_A*H[1] + C_B*H[2] - C_C*H[3])
#define HP2(H) (-C_C*H[4] + C_B*H[5] + C_A*H[6])
#define HP3(H) (-C_F*H[0] + C_E*H[1] - C_D*H[2])

__device__ __half g_z128[128 * 128 * 128];
__device__ __half g_z256[128 * 256 * 256];

__device__ __forceinline__ int refl(int i, int n) {
    i = (i < 0) ? (-1 - i) : i;
    return (i >= n) ? (2 * n - 1 - i) : i;
}

__device__ __forceinline__ float  ld1(const float* p)   { return __ldg(p); }
__device__ __forceinline__ float  ld1(const __half* p)  { return __half2float(__ldg(p)); }
__device__ __forceinline__ float2 ld2(const float2* p)  { return __ldg(p); }
__device__ __forceinline__ float2 ld2(const __half2* p) { return __half22float2(__ldg(p)); }

__device__ __forceinline__ uint2 pack2(__half2 a, __half2 b) {
    uint2 r;
    r.x = *reinterpret_cast<const unsigned*>(&a);
    r.y = *reinterpret_cast<const unsigned*>(&b);
    return r;
}

template <typename T> struct vec2of;
template <> struct vec2of<float>  { using t = float2; };
template <> struct vec2of<__half> { using t = __half2; };

// ===========================================================================
// Scalar column-upsample helpers (split y1 / y2), writing into smem (half*).
// ===========================================================================
template <int RI, int CI, typename TZ>
__device__ void colup_s_y1(const TZ* __restrict__ z, const float* __restrict__ yh,
                           __half* o, int rs, int b, int n, int jc) {
    constexpr int rh = RI / 2;
    const int d8[8] = {-4, -2, 0, 2, -1, 1, 3, 5};
    int pj = jc & 1;
    int rw[8], oB[8];
    float s1v[8], s2v[8];
#pragma unroll
    for (int t = 0; t < 8; t++) {
        int rr = refl(2 * n + d8[t], RI);
        rw[t] = rr;
        int ii = rr >> 1, pi = rr & 1;
        oB[t] = ii * CI + (pi ^ pj);
        s1v[t] = (pi & pj) ? -1.f : 1.f;
        s2v[t] = (pi & (pj ^ 1)) ? -1.f : 1.f;
    }
    const TZ* zb = z + (size_t)b * RI * CI + jc;
    const float* yb = yh + (size_t)b * 6 * rh * CI + 2 * (jc >> 1);
    const int sb = rh * CI;
    float L[8], H[8];
#pragma unroll
    for (int t = 0; t < 8; t++) L[t] = ld1(zb + rw[t] * CI);
#pragma unroll
    for (int t = 0; t < 8; t++)
        H[t] = s1v[t] * __ldg(yb + oB[t]) + s2v[t] * __ldg(yb + 5 * sb + oB[t]);  // lh
    o[0]      = __float2half(LP0(L) + SH * HP0(H));
    o[rs]     = __float2half(LP1(L) + SH * HP1(H));
    o[2 * rs] = __float2half(LP2(L) + SH * HP2(H));
    o[3 * rs] = __float2half(LP3(L) + SH * HP3(H));
}

template <int RI, int CI>
__device__ void colup_s_y2(const float* __restrict__ yh,
                           __half* o, int rs, int b, int n, int jc) {
    constexpr int rh = RI / 2;
    const int d8[8] = {-4, -2, 0, 2, -1, 1, 3, 5};
    int pj = jc & 1;
    int oB[8];
    float s1v[8], s2v[8];
#pragma unroll
    for (int t = 0; t < 8; t++) {
        int rr = refl(2 * n + d8[t], RI);
        int ii = rr >> 1, pi = rr & 1;
        oB[t] = ii * CI + (pi ^ pj);
        s1v[t] = (pi & pj) ? -1.f : 1.f;
        s2v[t] = (pi & (pj ^ 1)) ? -1.f : 1.f;
    }
    const float* yb = yh + (size_t)b * 6 * rh * CI + 2 * (jc >> 1);
    const int sb = rh * CI;
    float A[8], B[8];
#pragma unroll
    for (int t = 0; t < 8; t++) {
        A[t] = s1v[t] * __ldg(yb + 2 * sb + oB[t]) + s2v[t] * __ldg(yb + 3 * sb + oB[t]); // hl
        B[t] = s1v[t] * __ldg(yb + 1 * sb + oB[t]) + s2v[t] * __ldg(yb + 4 * sb + oB[t]); // hh
    }
    o[0]      = __float2half(SH * (LP0(A) + HP0(B)));
    o[rs]     = __float2half(SH * (LP1(A) + HP1(B)));
    o[2 * rs] = __float2half(SH * (LP2(A) + HP2(B)));
    o[3 * rs] = __float2half(SH * (LP3(A) + HP3(B)));
}

// ===========================================================================
// kABf: fused upsampling level. z:(128,RI,CI) -> Z:(128,2RI,2CI).
// Tile: 32 out rows x 64 out cols. smem y tiles: 32 x 21 half2 (+pad).
// ===========================================================================
template <int RI, int CI, typename TZ>
__global__ void __launch_bounds__(256)
kABf(const TZ* __restrict__ z, const float* __restrict__ yh,
     __half* __restrict__ Z) {
    constexpr int rh = RI / 2, ch = CI / 2, CO = 2 * CI;
    constexpr int SROW = 22;  // half2 row stride
    __shared__ __half2 y1s[32 * SROW];
    __shared__ __half2 y2s[32 * SROW];
    using TZ2 = typename vec2of<TZ>::t;
    int b = blockIdx.z;
    int i0 = blockIdx.y * 32;
    int u0 = blockIdx.x * 64;
    int n0 = i0 >> 2, c0h = u0 >> 1;
    int tid = threadIdx.x;

    const TZ2* zb2 = (const TZ2*)z + (size_t)b * RI * ch;
    const float2* yb2 = (const float2*)yh + (size_t)b * 6 * rh * ch;
    const int sstr = rh * ch;

#define LOAD_PAIR5(S1, S2, B0, B1)                                            \
    {                                                                         \
        float2 w1[5], w2[5];                                                  \
        _Pragma("unroll") for (int t = 0; t < 5; t++) {                       \
            w1[t] = __ldg(yb2j + ((S1) * sstr + (n_g - 2 + t) * ch));         \
            w2[t] = __ldg(yb2j + ((S2) * sstr + (n_g - 2 + t) * ch));         \
        }                                                                     \
        _Pragma("unroll") for (int t = 0; t < 4; t++) {                       \
            B0[t] = w1[t].x + w2[t].x;                                        \
            B1[t] = w1[t].y + w2[t].y;                                        \
            B0[4 + t] = w1[t + 1].y - w2[t + 1].y;                            \
            B1[4 + t] = w2[t + 1].x - w1[t + 1].x;                            \
        }                                                                     \
    }

    for (int it = tid; it < 336; it += 256) {
        int isy2 = it >= 168;
        int i2 = it - (isy2 ? 168 : 0);
        int cp = i2 % 21;
        int n_l = i2 / 21;
        int n_g = n0 + n_l;
        int e = c0h - 4 + 2 * cp;
        if (e >= 0 && e + 1 < CI && n_g >= 2 && n_g <= rh - 3) {
            int jj = e >> 1;
            const float2* yb2j = yb2 + jj;
            if (!isy2) {
                const TZ2* zc = zb2 + jj;
                int base = 2 * n_g;
                float2 Lz[8];
                Lz[0] = ld2(zc + (base - 4) * ch);
                Lz[1] = ld2(zc + (base - 2) * ch);
                Lz[2] = ld2(zc + base * ch);
                Lz[3] = ld2(zc + (base + 2) * ch);
                Lz[4] = ld2(zc + (base - 1) * ch);
                Lz[5] = ld2(zc + (base + 1) * ch);
                Lz[6] = ld2(zc + (base + 3) * ch);
                Lz[7] = ld2(zc + (base + 5) * ch);
                float L0[8], L1[8];
#pragma unroll
                for (int t = 0; t < 8; t++) { L0[t] = Lz[t].x; L1[t] = Lz[t].y; }
                float H0[8], H1[8];
                LOAD_PAIR5(0, 5, H0, H1);  // lh
                __half2* o = y1s + (4 * n_l) * SROW + cp;
                o[0]        = __floats2half2_rn(LP0(L0) + SH * HP0(H0), LP0(L1) + SH * HP0(H1));
                o[SROW]     = __floats2half2_rn(LP1(L0) + SH * HP1(H0), LP1(L1) + SH * HP1(H1));
                o[2 * SROW] = __floats2half2_rn(LP2(L0) + SH * HP2(H0), LP2(L1) + SH * HP2(H1));
                o[3 * SROW] = __floats2half2_rn(LP3(L0) + SH * HP3(H0), LP3(L1) + SH * HP3(H1));
            } else {
                float A0[8], A1[8], B0[8], B1[8];
                LOAD_PAIR5(2, 3, A0, A1);  // hl
                LOAD_PAIR5(1, 4, B0, B1);  // hh
                __half2* o = y2s + (4 * n_l) * SROW + cp;
                o[0]        = __floats2half2_rn(SH * (LP0(A0) + HP0(B0)), SH * (LP0(A1) + HP0(B1)));
                o[SROW]     = __floats2half2_rn(SH * (LP1(A0) + HP1(B0)), SH * (LP1(A1) + HP1(B1)));
                o[2 * SROW] = __floats2half2_rn(SH * (LP2(A0) + HP2(B0)), SH * (LP2(A1) + HP2(B1)));
                o[3 * SROW] = __floats2half2_rn(SH * (LP3(A0) + HP3(B0)), SH * (LP3(A1) + HP3(B1)));
            }
        } else {
#pragma unroll
            for (int s = 0; s < 2; s++) {
                int jc = refl(e + s, CI);
                __half* oh = (__half*)(isy2 ? y2s : y1s) + (4 * n_l) * (2 * SROW) + 2 * cp + s;
                if (!isy2) colup_s_y1<RI, CI, TZ>(z, yh, oh, 2 * SROW, b, n_g, jc);
                else       colup_s_y2<RI, CI>(yh, oh, 2 * SROW, b, n_g, jc);
            }
        }
    }
#undef LOAD_PAIR5
    __syncthreads();

    // -------- phase 2: row upsampling out of smem, 512 items --------
    size_t rowbase = (size_t)b * 2 * RI + i0;
#pragma unroll
    for (int hh = 0; hh < 2; hh++) {
        int it = tid + hh * 256;
        int p = it & 15, i_l = it >> 4;
        const __half2* q1 = y1s + i_l * SROW + p;
        const __half2* q2 = y2s + i_l * SROW + p;
        float2 a0 = __half22float2(q1[0]), a1 = __half22float2(q1[1]),
               a2 = __half22float2(q1[2]), a3 = __half22float2(q1[3]),
               a4 = __half22float2(q1[4]);
        float2 c0 = __half22float2(q2[0]), c1 = __half22float2(q2[1]),
               c2 = __half22float2(q2[2]), c3 = __half22float2(q2[3]),
               c4 = __half22float2(q2[4]);
        float L[8], H[8];
        L[0] = a0.x; L[1] = a1.x; L[2] = a2.x; L[3] = a3.x;
        L[4] = a1.y; L[5] = a2.y; L[6] = a3.y; L[7] = a4.y;
        H[0] = c0.x; H[1] = c1.x; H[2] = c2.x; H[3] = c3.x;
        H[4] = c1.y; H[5] = c2.y; H[6] = c3.y; H[7] = c4.y;
        __half2 ha = __floats2half2_rn(LP0(L) + HP0(H), LP1(L) + HP1(H));
        __half2 hb = __floats2half2_rn(LP2(L) + HP2(H), LP3(L) + HP3(H));
        reinterpret_cast<uint2*>(Z + (rowbase + i_l) * CO + u0)[p] = pack2(ha, hb);
    }
}

// ===========================================================================
// Scalar final-level column helpers (split), writing 2 rows into smem.
// ===========================================================================
template <int RI, int CI>
__device__ void colfin_s_y1(const __half* __restrict__ z, const float* __restrict__ yh,
                            __half* o, int rs, int b, int m, int jc) {
    constexpr int rh = RI / 2;
    int i0 = 2 * m;
    int pj = jc & 1;
    int o6[6];
    float s1v[6], s2v[6];
    int rr[6];
#pragma unroll
    for (int t = 0; t < 6; t++) {
        int rx = refl(i0 - 2 + t, RI);
        rr[t] = rx;
        int ii = rx >> 1, pi = rx & 1;
        o6[t] = ii * CI + (pi ^ pj);
        s1v[t] = (pi & pj) ? -1.f : 1.f;
        s2v[t] = (pi & (pj ^ 1)) ? -1.f : 1.f;
    }
    const __half* zb = z + (size_t)b * RI * CI + jc;
    const float* yb = yh + (size_t)b * 6 * rh * CI + 2 * (jc >> 1);
    const int sb = rh * CI;
    float zr[4];
#pragma unroll
    for (int t = 0; t < 4; t++) zr[t] = ld1(zb + rr[t + 1] * CI);
    float lr[6];
#pragma unroll
    for (int t = 0; t < 6; t++)
        lr[t] = s1v[t] * __ldg(yb + o6[t]) + s2v[t] * __ldg(yb + 5 * sb + o6[t]);
    o[0]  = __float2half(G0 * (zr[0] + zr[2]) + G1 * zr[1]
          + SH * (Q_E * (lr[0] + lr[4]) + Q_D * (lr[1] + lr[3]) + Q_F * lr[2]));
    o[rs] = __float2half(G0 * (zr[1] + zr[3]) + G1 * zr[2]
          + SH * (Q_E * (lr[1] + lr[5]) + Q_D * (lr[2] + lr[4]) + Q_F * lr[3]));
}

template <int RI, int CI>
__device__ void colfin_s_y2(const float* __restrict__ yh,
                            __half* o, int rs, int b, int m, int jc) {
    constexpr int rh = RI / 2;
    int i0 = 2 * m;
    int pj = jc & 1;
    int o6[6];
    float s1v[6], s2v[6];
#pragma unroll
    for (int t = 0; t < 6; t++) {
        int rx = refl(i0 - 2 + t, RI);
        int ii = rx >> 1, pi = rx & 1;
        o6[t] = ii * CI + (pi ^ pj);
        s1v[t] = (pi & pj) ? -1.f : 1.f;
        s2v[t] = (pi & (pj ^ 1)) ? -1.f : 1.f;
    }
    const float* yb = yh + (size_t)b * 6 * rh * CI + 2 * (jc >> 1);
    const int sb = rh * CI;
    float hlr[6], hhr[6];
#pragma unroll
    for (int t = 0; t < 6; t++) {
        hlr[t] = s1v[t] * __ldg(yb + 2 * sb + o6[t]) + s2v[t] * __ldg(yb + 3 * sb + o6[t]);
        hhr[t] = s1v[t] * __ldg(yb + 1 * sb + o6[t]) + s2v[t] * __ldg(yb + 4 * sb + o6[t]);
    }
    o[0]  = __float2half(SH * (G0 * (hlr[1] + hlr[3]) + G1 * hlr[2]
          + Q_E * (hhr[0] + hhr[4]) + Q_D * (hhr[1] + hhr[3]) + Q_F * hhr[2]));
    o[rs] = __float2half(SH * (G0 * (hlr[2] + hlr[4]) + G1 * hlr[3]
          + Q_E * (hhr[1] + hhr[5]) + Q_D * (hhr[2] + hhr[4]) + Q_F * hhr[3]));
}

// ===========================================================================
// kCDf: fused final level. z:(128,RI,CI), yh0 -> out:(128,RI,CI) fp32.
// Tile: 32 x 32 out. smem y tiles: 32 x 18 half2 (+pad).
// ===========================================================================
template <int RI, int CI>
__global__ void __launch_bounds__(256)
kCDf(const __half* __restrict__ z, const float* __restrict__ yh,
     float* __restrict__ out) {
    constexpr int rh = RI / 2, chb = CI / 2, MP = rh / 2;
    constexpr int SROW = 19;
    __shared__ __half2 y1s[32 * SROW];
    __shared__ __half2 y2s[32 * SROW];
    int b = blockIdx.z;
    int i0 = blockIdx.y * 32;
    int u0 = blockIdx.x * 32;
    int mp0 = i0 >> 2;
    int tid = threadIdx.x;

    const __half2* zb2 = (const __half2*)z + (size_t)b * RI * chb;
    const float2* yb2 = (const float2*)yh + (size_t)b * 6 * rh * chb;
    const int sstr = rh * chb;

#define LOAD_PAIR4(S1, S2, B0, B1)                                            \
    {                                                                         \
        float2 w1[4], w2[4];                                                  \
        _Pragma("unroll") for (int t = 0; t < 4; t++) {                       \
            w1[t] = __ldg(yb2j + ((S1) * sstr + (mm - 1 + t) * chb));         \
            w2[t] = __ldg(yb2j + ((S2) * sstr + (mm - 1 + t) * chb));         \
        }                                                                     \
        _Pragma("unroll") for (int t = 0; t < 4; t++) {                       \
            B0[2 * t] = w1[t].x + w2[t].x;                                    \
            B1[2 * t] = w1[t].y + w2[t].y;                                    \
            B0[2 * t + 1] = w1[t].y - w2[t].y;                                \
            B1[2 * t + 1] = w2[t].x - w1[t].x;                                \
        }                                                                     \
    }

    for (int it = tid; it < 288; it += 256) {
        int isy2 = it >= 144;
        int i2 = it - (isy2 ? 144 : 0);
        int cp = i2 % 18;
        int mp_l = i2 / 18;
        int mp_g = mp0 + mp_l;
        int mm = 2 * mp_g;
        int e = u0 - 2 + 2 * cp;
        if (e >= 0 && e + 1 < CI && mp_g >= 1 && mp_g <= MP - 2) {
            int jj = e >> 1;
            const float2* yb2j = yb2 + jj;
            int i0g = 2 * mm;
            if (!isy2) {
                float2 zr[6];
#pragma unroll
                for (int t = 0; t < 6; t++) zr[t] = ld2(zb2 + jj + (i0g - 1 + t) * chb);
                float lr0[8], lr1[8];
                LOAD_PAIR4(0, 5, lr0, lr1);
                __half2* o = y1s + (4 * mp_l) * SROW + cp;
#pragma unroll
                for (int q = 0; q < 4; q++) {
                    o[q * SROW] = __floats2half2_rn(
                        G0 * (zr[q].x + zr[q + 2].x) + G1 * zr[q + 1].x
                      + SH * (Q_E * (lr0[q] + lr0[q + 4]) + Q_D * (lr0[q + 1] + lr0[q + 3]) + Q_F * lr0[q + 2]),
                        G0 * (zr[q].y + zr[q + 2].y) + G1 * zr[q + 1].y
                      + SH * (Q_E * (lr1[q] + lr1[q + 4]) + Q_D * (lr1[q + 1] + lr1[q + 3]) + Q_F * lr1[q + 2]));
                }
            } else {
                float hl0[8], hl1[8], hh0[8], hh1[8];
                LOAD_PAIR4(2, 3, hl0, hl1);
                LOAD_PAIR4(1, 4, hh0, hh1);
                __half2* o = y2s + (4 * mp_l) * SROW + cp;
#pragma unroll
                for (int q = 0; q < 4; q++) {
                    o[q * SROW] = __floats2half2_rn(
                        SH * (G0 * (hl0[q + 1] + hl0[q + 3]) + G1 * hl0[q + 2]
                      + Q_E * (hh0[q] + hh0[q + 4]) + Q_D * (hh0[q + 1] + hh0[q + 3]) + Q_F * hh0[q + 2]),
                        SH * (G0 * (hl1[q + 1] + hl1[q + 3]) + G1 * hl1[q + 2]
                      + Q_E * (hh1[q] + hh1[q + 4]) + Q_D * (hh1[q + 1] + hh1[q + 3]) + Q_F * hh1[q + 2]));
                }
            }
        } else {
#pragma unroll
            for (int dm = 0; dm < 2; dm++) {
#pragma unroll
                for (int s = 0; s < 2; s++) {
                    int jc = refl(e + s, CI);
                    __half* oh = (__half*)(isy2 ? y2s : y1s)
                               + (4 * mp_l + 2 * dm) * (2 * SROW) + 2 * cp + s;
                    if (!isy2) colfin_s_y1<RI, CI>(z, yh, oh, 2 * SROW, b, mm + dm, jc);
                    else       colfin_s_y2<RI, CI>(yh, oh, 2 * SROW, b, mm + dm, jc);
                }
            }
        }
    }
#undef LOAD_PAIR4
    __syncthreads();

    // -------- phase 2: row filter out of smem, 256 items --------
    {
        int p = tid & 7, i_l = tid >> 3;
        const __half2* q1 = y1s + i_l * SROW + 2 * p;
        const __half2* q2 = y2s + i_l * SROW + 2 * p;
        float2 f0 = __half22float2(q1[0]), f1 = __half22float2(q1[1]),
               f2 = __half22float2(q1[2]), f3 = __half22float2(q1[3]);
        float2 g0 = __half22float2(q2[0]), g1 = __half22float2(q2[1]),
               g2 = __half22float2(q2[2]), g3 = __half22float2(q2[3]);
        float a[6], v[8];
        a[0] = f0.y; a[1] = f1.x; a[2] = f1.y; a[3] = f2.x; a[4] = f2.y; a[5] = f3.x;
        v[0] = g0.x; v[1] = g0.y; v[2] = g1.x; v[3] = g1.y;
        v[4] = g2.x; v[5] = g2.y; v[6] = g3.x; v[7] = g3.y;
        float4 o;
        o.x = G0 * (a[0] + a[2]) + G1 * a[1] + Q_E * (v[0] + v[4]) + Q_D * (v[1] + v[3]) + Q_F * v[2];
        o.y = G0 * (a[1] + a[3]) + G1 * a[2] + Q_E * (v[1] + v[5]) + Q_D * (v[2] + v[4]) + Q_F * v[3];
        o.z = G0 * (a[2] + a[4]) + G1 * a[3] + Q_E * (v[2] + v[6]) + Q_D * (v[3] + v[5]) + Q_F * v[4];
        o.w = G0 * (a[3] + a[5]) + G1 * a[4] + Q_E * (v[3] + v[7]) + Q_D * (v[4] + v[6]) + Q_F * v[5];
        reinterpret_cast<float4*>(out + ((size_t)b * RI + i0 + i_l) * CI + u0)[p] = o;
    }
}

extern "C" void kernel_launch(void* const* d_in, const int* in_sizes, int n_in,
                              void* d_out, int out_size) {
    const float *yl = nullptr, *yh0 = nullptr, *yh1 = nullptr, *yh2 = nullptr;
    for (int i = 0; i < n_in; i++) {
        switch (in_sizes[i]) {
            case 524288:   yl  = (const float*)d_in[i]; break;  // 128*64*64
            case 25165824: yh0 = (const float*)d_in[i]; break;  // 128*6*128*128*2
            case 6291456:  yh1 = (const float*)d_in[i]; break;  // 128*6*64*64*2
            case 1572864:  yh2 = (const float*)d_in[i]; break;  // 128*6*32*32*2
            default: break;
        }
    }

    __half *pz128, *pz256;
    cudaGetSymbolAddress((void**)&pz128, g_z128);
    cudaGetSymbolAddress((void**)&pz256, g_z256);

    // Level 1: (64,64) -> (128,128)
    kABf<64, 64, float><<<dim3(2, 4, 128), 256>>>(yl, yh2, pz128);
    // Level 2: (128,128) -> (256,256)
    kABf<128, 128, __half><<<dim3(4, 8, 128), 256>>>(pz128, yh1, pz256);
    // Final level -> out
    kCDf<256, 256><<<dim3(8, 8, 128), 256>>>(pz256, yh0, (float*)d_out);
}

// round 11
// speedup vs baseline: 1.0490x; 1.0490x over previous
#include <cuda_runtime.h>
#include <cuda_fp16.h>

// ---------------------------------------------------------------------------
// Inverse DTCWT, 3 levels. HYBRID: split kA/kB (interleaved padded yp buffer)
// for the two upsampling levels, fused kCDf (smem) for the final level.
// fp16 intermediates, fp32 compute.
// ---------------------------------------------------------------------------

#define SH   0.70710678118654752440f
#define C_A  0.23389032f
#define C_B  0.5875183f
#define C_C  0.11430184f
#define C_D  0.76027237f
#define C_E  0.08832942f
#define C_F  0.03516384f

#define G0   0.35355339059327f
#define G1   0.70710678118655f
#define Q_E  (-0.08838834764832f)
#define Q_D  (-0.17677669529664f)
#define Q_F  0.53033008588991f

#define LP0(L) ( C_A*L[1] + C_B*L[2] - C_C*L[3])
#define LP1(L) ( C_D*L[5] - C_E*L[6] + C_F*L[7])
#define LP2(L) ( C_F*L[0] - C_E*L[1] + C_D*L[2])
#define LP3(L) (-C_C*L[4] + C_B*L[5] + C_A*L[6])
#define HP0(H) (-C_D*H[5] + C_E*H[6] - C_F*H[7])
#define HP1(H) ( C_A*H[1] + C_B*H[2] - C_C*H[3])
#define HP2(H) (-C_C*H[4] + C_B*H[5] + C_A*H[6])
#define HP3(H) (-C_F*H[0] + C_E*H[1] - C_D*H[2])

__device__ uint2  g_yp[128 * 256 * 134];
__device__ __half g_z128[128 * 128 * 128];
__device__ __half g_z256[128 * 256 * 256];

__device__ __forceinline__ int refl(int i, int n) {
    i = (i < 0) ? (-1 - i) : i;
    return (i >= n) ? (2 * n - 1 - i) : i;
}

__host__ __device__ constexpr int ilog2c(int v) { return v <= 1 ? 0 : 1 + ilog2c(v >> 1); }

__device__ __forceinline__ float  ld1(const float* p)   { return __ldg(p); }
__device__ __forceinline__ float  ld1(const __half* p)  { return __half2float(__ldg(p)); }
__device__ __forceinline__ float2 ld2(const float2* p)  { return __ldg(p); }
__device__ __forceinline__ float2 ld2(const __half2* p) { return __half22float2(__ldg(p)); }

__device__ __forceinline__ uint2 pack2(__half2 a, __half2 b) {
    uint2 r;
    r.x = *reinterpret_cast<const unsigned*>(&a);
    r.y = *reinterpret_cast<const unsigned*>(&b);
    return r;
}
__device__ __forceinline__ float2 unpk_lo(uint2 v) {
    __half2 h = *reinterpret_cast<const __half2*>(&v.x);
    return __half22float2(h);
}
__device__ __forceinline__ float2 unpk_hi(uint2 v) {
    __half2 h = *reinterpret_cast<const __half2*>(&v.y);
    return __half22float2(h);
}

template <typename T> struct vec2of;
template <> struct vec2of<float>  { using t = float2; };
template <> struct vec2of<__half> { using t = __half2; };

// ===========================================================================
// kA scalar path: writes single halves into interleaved layout.
// ===========================================================================
template <int RI, int CI, typename TZ>
__device__ void kA_scalar(const TZ* __restrict__ z, const float* __restrict__ yh,
                          uint2* __restrict__ yp, int b, int n, int jc, int pc) {
    constexpr int rh = RI / 2, PS2 = (CI + 12) / 2;
    const int d8[8] = {-4, -2, 0, 2, -1, 1, 3, 5};
    int pj = jc & 1;
    int rw[8], oB[8];
    float s1v[8], s2v[8];
#pragma unroll
    for (int t = 0; t < 8; t++) {
        int rr = refl(2 * n + d8[t], RI);
        rw[t] = rr;
        int ii = rr >> 1, pi = rr & 1;
        oB[t] = ii * CI + (pi ^ pj);
        s1v[t] = (pi & pj) ? -1.f : 1.f;
        s2v[t] = (pi & (pj ^ 1)) ? -1.f : 1.f;
    }
    const TZ* zb = z + (size_t)b * RI * CI + jc;
    const float* yb = yh + (size_t)b * 6 * rh * CI + 2 * (jc >> 1);
    const int sb = rh * CI;

    float L[8], H[8], A[8], B[8];
#pragma unroll
    for (int t = 0; t < 8; t++) L[t] = ld1(zb + rw[t] * CI);
#pragma unroll
    for (int t = 0; t < 8; t++) {
        H[t] = s1v[t] * __ldg(yb + oB[t]) + s2v[t] * __ldg(yb + 5 * sb + oB[t]);          // lh
        A[t] = s1v[t] * __ldg(yb + 2 * sb + oB[t]) + s2v[t] * __ldg(yb + 3 * sb + oB[t]); // hl
        B[t] = s1v[t] * __ldg(yb + 1 * sb + oB[t]) + s2v[t] * __ldg(yb + 4 * sb + oB[t]); // hh
    }

    __half* o = (__half*)yp + (((size_t)b * 2 * RI + 4 * n) * PS2 + (pc >> 1)) * 4 + (pc & 1);
    const int rs = PS2 * 4;
    o[0]          = __float2half(LP0(L) + SH * HP0(H));
    o[2]          = __float2half(SH * (LP0(A) + HP0(B)));
    o[rs]         = __float2half(LP1(L) + SH * HP1(H));
    o[rs + 2]     = __float2half(SH * (LP1(A) + HP1(B)));
    o[2 * rs]     = __float2half(LP2(L) + SH * HP2(H));
    o[2 * rs + 2] = __float2half(SH * (LP2(A) + HP2(B)));
    o[3 * rs]     = __float2half(LP3(L) + SH * HP3(H));
    o[3 * rs + 2] = __float2half(SH * (LP3(A) + HP3(B)));
}

// ===========================================================================
// kA: column upsampling -> interleaved padded buffer, cols 4..CI+9.
// ===========================================================================
template <int RI, int CI, typename TZ>
__global__ void __launch_bounds__(256)
kA(const TZ* __restrict__ z, const float* __restrict__ yh,
   uint2* __restrict__ yp) {
    constexpr int rh = RI / 2, ch = CI / 2, JP = ch + 5, PS2 = (CI + 12) / 2;
    using TZ2 = typename vec2of<TZ>::t;
    unsigned idx = blockIdx.x * 256u + threadIdx.x;
    int jp = idx % JP;
    int n = (idx / JP) % rh;
    int b = idx / (JP * rh);

    if (jp < ch && n >= 2 && n <= rh - 3) {
        const TZ2* z2 = (const TZ2*)z + (size_t)b * RI * ch + jp;
        const float2* yb2 = (const float2*)yh + (size_t)b * 6 * rh * ch + jp;
        const int sstr = rh * ch;
        int base = 2 * n;

        float2 Lz[8];
        Lz[0] = ld2(z2 + (base - 4) * ch);
        Lz[1] = ld2(z2 + (base - 2) * ch);
        Lz[2] = ld2(z2 + base * ch);
        Lz[3] = ld2(z2 + (base + 2) * ch);
        Lz[4] = ld2(z2 + (base - 1) * ch);
        Lz[5] = ld2(z2 + (base + 1) * ch);
        Lz[6] = ld2(z2 + (base + 3) * ch);
        Lz[7] = ld2(z2 + (base + 5) * ch);
        float L0[8], L1[8];
#pragma unroll
        for (int t = 0; t < 8; t++) { L0[t] = Lz[t].x; L1[t] = Lz[t].y; }

#define LOAD_PAIR5(S1, S2, B0, B1)                                            \
    {                                                                         \
        float2 w1[5], w2[5];                                                  \
        _Pragma("unroll") for (int t = 0; t < 5; t++) {                       \
            w1[t] = __ldg(yb2 + ((S1) * sstr + (n - 2 + t) * ch));            \
            w2[t] = __ldg(yb2 + ((S2) * sstr + (n - 2 + t) * ch));            \
        }                                                                     \
        _Pragma("unroll") for (int t = 0; t < 4; t++) {                       \
            B0[t] = w1[t].x + w2[t].x;                                        \
            B1[t] = w1[t].y + w2[t].y;                                        \
            B0[4 + t] = w1[t + 1].y - w2[t + 1].y;                            \
            B1[4 + t] = w2[t + 1].x - w1[t + 1].x;                            \
        }                                                                     \
    }
        float H0[8], H1[8], A0[8], A1[8], B0[8], B1[8];
        LOAD_PAIR5(0, 5, H0, H1);  // lh
        LOAD_PAIR5(2, 3, A0, A1);  // hl
        LOAD_PAIR5(1, 4, B0, B1);  // hh
#undef LOAD_PAIR5

        uint2* o = yp + ((size_t)b * 2 * RI + 4 * n) * PS2 + (jp + 2);
        o[0] = pack2(__floats2half2_rn(LP0(L0) + SH * HP0(H0), LP0(L1) + SH * HP0(H1)),
                     __floats2half2_rn(SH * (LP0(A0) + HP0(B0)), SH * (LP0(A1) + HP0(B1))));
        o[PS2] = pack2(__floats2half2_rn(LP1(L0) + SH * HP1(H0), LP1(L1) + SH * HP1(H1)),
                       __floats2half2_rn(SH * (LP1(A0) + HP1(B0)), SH * (LP1(A1) + HP1(B1))));
        o[2 * PS2] = pack2(__floats2half2_rn(LP2(L0) + SH * HP2(H0), LP2(L1) + SH * HP2(H1)),
                           __floats2half2_rn(SH * (LP2(A0) + HP2(B0)), SH * (LP2(A1) + HP2(B1))));
        o[3 * PS2] = pack2(__floats2half2_rn(LP3(L0) + SH * HP3(H0), LP3(L1) + SH * HP3(H1)),
                           __floats2half2_rn(SH * (LP3(A0) + HP3(B0)), SH * (LP3(A1) + HP3(B1))));
    } else if (jp < ch) {
        kA_scalar<RI, CI, TZ>(z, yh, yp, b, n, 2 * jp, 2 * jp + 4);
        kA_scalar<RI, CI, TZ>(z, yh, yp, b, n, 2 * jp + 1, 2 * jp + 5);
    } else {
        int hp = jp - ch;
        int pc0 = (hp < 2) ? 2 * hp : (CI + 2 * hp);
#pragma unroll
        for (int s = 0; s < 2; s++) {
            int pc = pc0 + s;
            int jc = refl(pc - 4, CI);
            kA_scalar<RI, CI, TZ>(z, yh, yp, b, n, jc, pc);
        }
    }
}

// ===========================================================================
// kB: branch-free row upsampling, 2 rows/thread, 5 uint2 loads per row.
// ===========================================================================
template <int RO, int CO>
__global__ void __launch_bounds__(256)
kB(const uint2* __restrict__ yp, __half* __restrict__ Z) {
    constexpr int ch = CO / 4;
    constexpr int PS2 = (CO / 2 + 12) / 2;
    constexpr int LCH = ilog2c(ch);
    unsigned idx = blockIdx.x * 256u + threadIdx.x;
    int n = idx & (ch - 1);
    int rp = idx >> LCH;
    int row0 = 2 * rp;

#pragma unroll
    for (int rr = 0; rr < 2; rr++) {
        int row = row0 + rr;
        const uint2* q = yp + (size_t)row * PS2 + n;
        uint2 v0 = __ldg(q), v1 = __ldg(q + 1), v2 = __ldg(q + 2),
              v3 = __ldg(q + 3), v4 = __ldg(q + 4);
        float2 u0 = unpk_lo(v0), u1 = unpk_lo(v1), u2 = unpk_lo(v2),
               u3 = unpk_lo(v3), u4 = unpk_lo(v4);
        float2 w0 = unpk_hi(v0), w1 = unpk_hi(v1), w2 = unpk_hi(v2),
               w3 = unpk_hi(v3), w4 = unpk_hi(v4);
        float L[8], H[8];
        L[0] = u0.x; L[1] = u1.x; L[2] = u2.x; L[3] = u3.x;
        L[4] = u1.y; L[5] = u2.y; L[6] = u3.y; L[7] = u4.y;
        H[0] = w0.x; H[1] = w1.x; H[2] = w2.x; H[3] = w3.x;
        H[4] = w1.y; H[5] = w2.y; H[6] = w3.y; H[7] = w4.y;

        __half2 ha = __floats2half2_rn(LP0(L) + HP0(H), LP1(L) + HP1(H));
        __half2 hb = __floats2half2_rn(LP2(L) + HP2(H), LP3(L) + HP3(H));
        reinterpret_cast<uint2*>(Z + (size_t)row * CO)[n] = pack2(ha, hb);
    }
}

// ===========================================================================
// Scalar final-level column helpers (split), writing 2 rows into smem.
// ===========================================================================
template <int RI, int CI>
__device__ void colfin_s_y1(const __half* __restrict__ z, const float* __restrict__ yh,
                            __half* o, int rs, int b, int m, int jc) {
    constexpr int rh = RI / 2;
    int i0 = 2 * m;
    int pj = jc & 1;
    int o6[6];
    float s1v[6], s2v[6];
    int rr[6];
#pragma unroll
    for (int t = 0; t < 6; t++) {
        int rx = refl(i0 - 2 + t, RI);
        rr[t] = rx;
        int ii = rx >> 1, pi = rx & 1;
        o6[t] = ii * CI + (pi ^ pj);
        s1v[t] = (pi & pj) ? -1.f : 1.f;
        s2v[t] = (pi & (pj ^ 1)) ? -1.f : 1.f;
    }
    const __half* zb = z + (size_t)b * RI * CI + jc;
    const float* yb = yh + (size_t)b * 6 * rh * CI + 2 * (jc >> 1);
    const int sb = rh * CI;
    float zr[4];
#pragma unroll
    for (int t = 0; t < 4; t++) zr[t] = ld1(zb + rr[t + 1] * CI);
    float lr[6];
#pragma unroll
    for (int t = 0; t < 6; t++)
        lr[t] = s1v[t] * __ldg(yb + o6[t]) + s2v[t] * __ldg(yb + 5 * sb + o6[t]);
    o[0]  = __float2half(G0 * (zr[0] + zr[2]) + G1 * zr[1]
          + SH * (Q_E * (lr[0] + lr[4]) + Q_D * (lr[1] + lr[3]) + Q_F * lr[2]));
    o[rs] = __float2half(G0 * (zr[1] + zr[3]) + G1 * zr[2]
          + SH * (Q_E * (lr[1] + lr[5]) + Q_D * (lr[2] + lr[4]) + Q_F * lr[3]));
}

template <int RI, int CI>
__device__ void colfin_s_y2(const float* __restrict__ yh,
                            __half* o, int rs, int b, int m, int jc) {
    constexpr int rh = RI / 2;
    int i0 = 2 * m;
    int pj = jc & 1;
    int o6[6];
    float s1v[6], s2v[6];
#pragma unroll
    for (int t = 0; t < 6; t++) {
        int rx = refl(i0 - 2 + t, RI);
        int ii = rx >> 1, pi = rx & 1;
        o6[t] = ii * CI + (pi ^ pj);
        s1v[t] = (pi & pj) ? -1.f : 1.f;
        s2v[t] = (pi & (pj ^ 1)) ? -1.f : 1.f;
    }
    const float* yb = yh + (size_t)b * 6 * rh * CI + 2 * (jc >> 1);
    const int sb = rh * CI;
    float hlr[6], hhr[6];
#pragma unroll
    for (int t = 0; t < 6; t++) {
        hlr[t] = s1v[t] * __ldg(yb + 2 * sb + o6[t]) + s2v[t] * __ldg(yb + 3 * sb + o6[t]);
        hhr[t] = s1v[t] * __ldg(yb + 1 * sb + o6[t]) + s2v[t] * __ldg(yb + 4 * sb + o6[t]);
    }
    o[0]  = __float2half(SH * (G0 * (hlr[1] + hlr[3]) + G1 * hlr[2]
          + Q_E * (hhr[0] + hhr[4]) + Q_D * (hhr[1] + hhr[3]) + Q_F * hhr[2]));
    o[rs] = __float2half(SH * (G0 * (hlr[2] + hlr[4]) + G1 * hlr[3]
          + Q_E * (hhr[1] + hhr[5]) + Q_D * (hhr[2] + hhr[4]) + Q_F * hhr[3]));
}

// ===========================================================================
// kCDf: fused final level. z:(128,RI,CI), yh0 -> out:(128,RI,CI) fp32.
// Tile: 32 x 32 out. smem y tiles: 32 x 18 half2 (+pad).
// ===========================================================================
template <int RI, int CI>
__global__ void __launch_bounds__(256)
kCDf(const __half* __restrict__ z, const float* __restrict__ yh,
     float* __restrict__ out) {
    constexpr int rh = RI / 2, chb = CI / 2, MP = rh / 2;
    constexpr int SROW = 19;
    __shared__ __half2 y1s[32 * SROW];
    __shared__ __half2 y2s[32 * SROW];
    int b = blockIdx.z;
    int i0 = blockIdx.y * 32;
    int u0 = blockIdx.x * 32;
    int mp0 = i0 >> 2;
    int tid = threadIdx.x;

    const __half2* zb2 = (const __half2*)z + (size_t)b * RI * chb;
    const float2* yb2 = (const float2*)yh + (size_t)b * 6 * rh * chb;
    const int sstr = rh * chb;

#define LOAD_PAIR4(S1, S2, B0, B1)                                            \
    {                                                                         \
        float2 w1[4], w2[4];                                                  \
        _Pragma("unroll") for (int t = 0; t < 4; t++) {                       \
            w1[t] = __ldg(yb2j + ((S1) * sstr + (mm - 1 + t) * chb));         \
            w2[t] = __ldg(yb2j + ((S2) * sstr + (mm - 1 + t) * chb));         \
        }                                                                     \
        _Pragma("unroll") for (int t = 0; t < 4; t++) {                       \
            B0[2 * t] = w1[t].x + w2[t].x;                                    \
            B1[2 * t] = w1[t].y + w2[t].y;                                    \
            B0[2 * t + 1] = w1[t].y - w2[t].y;                                \
            B1[2 * t + 1] = w2[t].x - w1[t].x;                                \
        }                                                                     \
    }

    for (int it = tid; it < 288; it += 256) {
        int isy2 = it >= 144;
        int i2 = it - (isy2 ? 144 : 0);
        int cp = i2 % 18;
        int mp_l = i2 / 18;
        int mp_g = mp0 + mp_l;
        int mm = 2 * mp_g;
        int e = u0 - 2 + 2 * cp;
        if (e >= 0 && e + 1 < CI && mp_g >= 1 && mp_g <= MP - 2) {
            int jj = e >> 1;
            const float2* yb2j = yb2 + jj;
            int i0g = 2 * mm;
            if (!isy2) {
                float2 zr[6];
#pragma unroll
                for (int t = 0; t < 6; t++) zr[t] = ld2(zb2 + jj + (i0g - 1 + t) * chb);
                float lr0[8], lr1[8];
                LOAD_PAIR4(0, 5, lr0, lr1);
                __half2* o = y1s + (4 * mp_l) * SROW + cp;
#pragma unroll
                for (int q = 0; q < 4; q++) {
                    o[q * SROW] = __floats2half2_rn(
                        G0 * (zr[q].x + zr[q + 2].x) + G1 * zr[q + 1].x
                      + SH * (Q_E * (lr0[q] + lr0[q + 4]) + Q_D * (lr0[q + 1] + lr0[q + 3]) + Q_F * lr0[q + 2]),
                        G0 * (zr[q].y + zr[q + 2].y) + G1 * zr[q + 1].y
                      + SH * (Q_E * (lr1[q] + lr1[q + 4]) + Q_D * (lr1[q + 1] + lr1[q + 3]) + Q_F * lr1[q + 2]));
                }
            } else {
                float hl0[8], hl1[8], hh0[8], hh1[8];
                LOAD_PAIR4(2, 3, hl0, hl1);
                LOAD_PAIR4(1, 4, hh0, hh1);
                __half2* o = y2s + (4 * mp_l) * SROW + cp;
#pragma unroll
                for (int q = 0; q < 4; q++) {
                    o[q * SROW] = __floats2half2_rn(
                        SH * (G0 * (hl0[q + 1] + hl0[q + 3]) + G1 * hl0[q + 2]
                      + Q_E * (hh0[q] + hh0[q + 4]) + Q_D * (hh0[q + 1] + hh0[q + 3]) + Q_F * hh0[q + 2]),
                        SH * (G0 * (hl1[q + 1] + hl1[q + 3]) + G1 * hl1[q + 2]
                      + Q_E * (hh1[q] + hh1[q + 4]) + Q_D * (hh1[q + 1] + hh1[q + 3]) + Q_F * hh1[q + 2]));
                }
            }
        } else {
#pragma unroll
            for (int dm = 0; dm < 2; dm++) {
#pragma unroll
                for (int s = 0; s < 2; s++) {
                    int jc = refl(e + s, CI);
                    __half* oh = (__half*)(isy2 ? y2s : y1s)
                               + (4 * mp_l + 2 * dm) * (2 * SROW) + 2 * cp + s;
                    if (!isy2) colfin_s_y1<RI, CI>(z, yh, oh, 2 * SROW, b, mm + dm, jc);
                    else       colfin_s_y2<RI, CI>(yh, oh, 2 * SROW, b, mm + dm, jc);
                }
            }
        }
    }
#undef LOAD_PAIR4
    __syncthreads();

    // -------- phase 2: row filter out of smem, 256 items --------
    {
        int p = tid & 7, i_l = tid >> 3;
        const __half2* q1 = y1s + i_l * SROW + 2 * p;
        const __half2* q2 = y2s + i_l * SROW + 2 * p;
        float2 f0 = __half22float2(q1[0]), f1 = __half22float2(q1[1]),
               f2 = __half22float2(q1[2]), f3 = __half22float2(q1[3]);
        float2 g0 = __half22float2(q2[0]), g1 = __half22float2(q2[1]),
               g2 = __half22float2(q2[2]), g3 = __half22float2(q2[3]);
        float a[6], v[8];
        a[0] = f0.y; a[1] = f1.x; a[2] = f1.y; a[3] = f2.x; a[4] = f2.y; a[5] = f3.x;
        v[0] = g0.x; v[1] = g0.y; v[2] = g1.x; v[3] = g1.y;
        v[4] = g2.x; v[5] = g2.y; v[6] = g3.x; v[7] = g3.y;
        float4 o;
        o.x = G0 * (a[0] + a[2]) + G1 * a[1] + Q_E * (v[0] + v[4]) + Q_D * (v[1] + v[3]) + Q_F * v[2];
        o.y = G0 * (a[1] + a[3]) + G1 * a[2] + Q_E * (v[1] + v[5]) + Q_D * (v[2] + v[4]) + Q_F * v[3];
        o.z = G0 * (a[2] + a[4]) + G1 * a[3] + Q_E * (v[2] + v[6]) + Q_D * (v[3] + v[5]) + Q_F * v[4];
        o.w = G0 * (a[3] + a[5]) + G1 * a[4] + Q_E * (v[3] + v[7]) + Q_D * (v[4] + v[6]) + Q_F * v[5];
        reinterpret_cast<float4*>(out + ((size_t)b * RI + i0 + i_l) * CI + u0)[p] = o;
    }
}

extern "C" void kernel_launch(void* const* d_in, const int* in_sizes, int n_in,
                              void* d_out, int out_size) {
    const float *yl = nullptr, *yh0 = nullptr, *yh1 = nullptr, *yh2 = nullptr;
    for (int i = 0; i < n_in; i++) {
        switch (in_sizes[i]) {
            case 524288:   yl  = (const float*)d_in[i]; break;  // 128*64*64
            case 25165824: yh0 = (const float*)d_in[i]; break;  // 128*6*128*128*2
            case 6291456:  yh1 = (const float*)d_in[i]; break;  // 128*6*64*64*2
            case 1572864:  yh2 = (const float*)d_in[i]; break;  // 128*6*32*32*2
            default: break;
        }
    }

    uint2* pyp;
    __half *pz128, *pz256;
    cudaGetSymbolAddress((void**)&pyp,   g_yp);
    cudaGetSymbolAddress((void**)&pz128, g_z128);
    cudaGetSymbolAddress((void**)&pz256, g_z256);

    // Level 1: (64,64) -> (128,128)
    kA<64, 64, float><<<128 * 32 * 37 / 256, 256>>>(yl, yh2, pyp);
    kB<128, 128><<<128 * 64 * 32 / 256, 256>>>(pyp, pz128);

    // Level 2: (128,128) -> (256,256)
    kA<128, 128, __half><<<128 * 64 * 69 / 256, 256>>>(pz128, yh1, pyp);
    kB<256, 256><<<128 * 128 * 64 / 256, 256>>>(pyp, pz256);

    // Final level: fused col+row -> out
    kCDf<256, 256><<<dim3(8, 8, 128), 256>>>(pz256, yh0, (float*)d_out);
}

// round 12
// speedup vs baseline: 1.0617x; 1.0121x over previous
#include <cuda_runtime.h>
#include <cuda_fp16.h>

// ---------------------------------------------------------------------------
// Inverse DTCWT, 3 levels. HYBRID: split kA/kB (interleaved padded yp buffer)
// for the two upsampling levels, fused kCDf (smem) for the final level.
// fp16 intermediates, fp32 compute.
// ---------------------------------------------------------------------------

#define SH   0.70710678118654752440f
#define C_A  0.23389032f
#define C_B  0.5875183f
#define C_C  0.11430184f
#define C_D  0.76027237f
#define C_E  0.08832942f
#define C_F  0.03516384f

#define G0   0.35355339059327f
#define G1   0.70710678118655f
#define Q_E  (-0.08838834764832f)
#define Q_D  (-0.17677669529664f)
#define Q_F  0.53033008588991f

#define LP0(L) ( C_A*L[1] + C_B*L[2] - C_C*L[3])
#define LP1(L) ( C_D*L[5] - C_E*L[6] + C_F*L[7])
#define LP2(L) ( C_F*L[0] - C_E*L[1] + C_D*L[2])
#define LP3(L) (-C_C*L[4] + C_B*L[5] + C_A*L[6])
#define HP0(H) (-C_D*H[5] + C_E*H[6] - C_F*H[7])
#define HP1(H) ( C_A*H[1] + C_B*H[2] - C_C*H[3])
#define HP2(H) (-C_C*H[4] + C_B*H[5] + C_A*H[6])
#define HP3(H) (-C_F*H[0] + C_E*H[1] - C_D*H[2])

__device__ uint2  g_yp[128 * 256 * 134];
__device__ __half g_z128[128 * 128 * 128];
__device__ __half g_z256[128 * 256 * 256];

__device__ __forceinline__ int refl(int i, int n) {
    i = (i < 0) ? (-1 - i) : i;
    return (i >= n) ? (2 * n - 1 - i) : i;
}

__host__ __device__ constexpr int ilog2c(int v) { return v <= 1 ? 0 : 1 + ilog2c(v >> 1); }

__device__ __forceinline__ float  ld1(const float* p)   { return __ldg(p); }
__device__ __forceinline__ float  ld1(const __half* p)  { return __half2float(__ldg(p)); }
__device__ __forceinline__ float2 ld2(const float2* p)  { return __ldg(p); }
__device__ __forceinline__ float2 ld2(const __half2* p) { return __half22float2(__ldg(p)); }

__device__ __forceinline__ uint2 pack2(__half2 a, __half2 b) {
    uint2 r;
    r.x = *reinterpret_cast<const unsigned*>(&a);
    r.y = *reinterpret_cast<const unsigned*>(&b);
    return r;
}
__device__ __forceinline__ float2 unpk_lo(uint2 v) {
    __half2 h = *reinterpret_cast<const __half2*>(&v.x);
    return __half22float2(h);
}
__device__ __forceinline__ float2 unpk_hi(uint2 v) {
    __half2 h = *reinterpret_cast<const __half2*>(&v.y);
    return __half22float2(h);
}

template <typename T> struct vec2of;
template <> struct vec2of<float>  { using t = float2; };
template <> struct vec2of<__half> { using t = __half2; };

// ===========================================================================
// kA scalar path: writes single halves into interleaved layout.
// ===========================================================================
template <int RI, int CI, typename TZ>
__device__ void kA_scalar(const TZ* __restrict__ z, const float* __restrict__ yh,
                          uint2* __restrict__ yp, int b, int n, int jc, int pc) {
    constexpr int rh = RI / 2, PS2 = (CI + 12) / 2;
    const int d8[8] = {-4, -2, 0, 2, -1, 1, 3, 5};
    int pj = jc & 1;
    int rw[8], oB[8];
    float s1v[8], s2v[8];
#pragma unroll
    for (int t = 0; t < 8; t++) {
        int rr = refl(2 * n + d8[t], RI);
        rw[t] = rr;
        int ii = rr >> 1, pi = rr & 1;
        oB[t] = ii * CI + (pi ^ pj);
        s1v[t] = (pi & pj) ? -1.f : 1.f;
        s2v[t] = (pi & (pj ^ 1)) ? -1.f : 1.f;
    }
    const TZ* zb = z + (size_t)b * RI * CI + jc;
    const float* yb = yh + (size_t)b * 6 * rh * CI + 2 * (jc >> 1);
    const int sb = rh * CI;

    float L[8], H[8], A[8], B[8];
#pragma unroll
    for (int t = 0; t < 8; t++) L[t] = ld1(zb + rw[t] * CI);
#pragma unroll
    for (int t = 0; t < 8; t++) {
        H[t] = s1v[t] * __ldg(yb + oB[t]) + s2v[t] * __ldg(yb + 5 * sb + oB[t]);          // lh
        A[t] = s1v[t] * __ldg(yb + 2 * sb + oB[t]) + s2v[t] * __ldg(yb + 3 * sb + oB[t]); // hl
        B[t] = s1v[t] * __ldg(yb + 1 * sb + oB[t]) + s2v[t] * __ldg(yb + 4 * sb + oB[t]); // hh
    }

    __half* o = (__half*)yp + (((size_t)b * 2 * RI + 4 * n) * PS2 + (pc >> 1)) * 4 + (pc & 1);
    const int rs = PS2 * 4;
    o[0]          = __float2half(LP0(L) + SH * HP0(H));
    o[2]          = __float2half(SH * (LP0(A) + HP0(B)));
    o[rs]         = __float2half(LP1(L) + SH * HP1(H));
    o[rs + 2]     = __float2half(SH * (LP1(A) + HP1(B)));
    o[2 * rs]     = __float2half(LP2(L) + SH * HP2(H));
    o[2 * rs + 2] = __float2half(SH * (LP2(A) + HP2(B)));
    o[3 * rs]     = __float2half(LP3(L) + SH * HP3(H));
    o[3 * rs + 2] = __float2half(SH * (LP3(A) + HP3(B)));
}

// ===========================================================================
// kA: column upsampling -> interleaved padded buffer, cols 4..CI+9.
// ===========================================================================
template <int RI, int CI, typename TZ>
__global__ void __launch_bounds__(256)
kA(const TZ* __restrict__ z, const float* __restrict__ yh,
   uint2* __restrict__ yp) {
    constexpr int rh = RI / 2, ch = CI / 2, JP = ch + 5, PS2 = (CI + 12) / 2;
    using TZ2 = typename vec2of<TZ>::t;
    unsigned idx = blockIdx.x * 256u + threadIdx.x;
    int jp = idx % JP;
    int n = (idx / JP) % rh;
    int b = idx / (JP * rh);

    if (jp < ch && n >= 2 && n <= rh - 3) {
        const TZ2* z2 = (const TZ2*)z + (size_t)b * RI * ch + jp;
        const float2* yb2 = (const float2*)yh + (size_t)b * 6 * rh * ch + jp;
        const int sstr = rh * ch;
        int base = 2 * n;

        float2 Lz[8];
        Lz[0] = ld2(z2 + (base - 4) * ch);
        Lz[1] = ld2(z2 + (base - 2) * ch);
        Lz[2] = ld2(z2 + base * ch);
        Lz[3] = ld2(z2 + (base + 2) * ch);
        Lz[4] = ld2(z2 + (base - 1) * ch);
        Lz[5] = ld2(z2 + (base + 1) * ch);
        Lz[6] = ld2(z2 + (base + 3) * ch);
        Lz[7] = ld2(z2 + (base + 5) * ch);
        float L0[8], L1[8];
#pragma unroll
        for (int t = 0; t < 8; t++) { L0[t] = Lz[t].x; L1[t] = Lz[t].y; }

#define LOAD_PAIR5(S1, S2, B0, B1)                                            \
    {                                                                         \
        float2 w1[5], w2[5];                                                  \
        _Pragma("unroll") for (int t = 0; t < 5; t++) {                       \
            w1[t] = __ldg(yb2 + ((S1) * sstr + (n - 2 + t) * ch));            \
            w2[t] = __ldg(yb2 + ((S2) * sstr + (n - 2 + t) * ch));            \
        }                                                                     \
        _Pragma("unroll") for (int t = 0; t < 4; t++) {                       \
            B0[t] = w1[t].x + w2[t].x;                                        \
            B1[t] = w1[t].y + w2[t].y;                                        \
            B0[4 + t] = w1[t + 1].y - w2[t + 1].y;                            \
            B1[4 + t] = w2[t + 1].x - w1[t + 1].x;                            \
        }                                                                     \
    }
        float H0[8], H1[8], A0[8], A1[8], B0[8], B1[8];
        LOAD_PAIR5(0, 5, H0, H1);  // lh
        LOAD_PAIR5(2, 3, A0, A1);  // hl
        LOAD_PAIR5(1, 4, B0, B1);  // hh
#undef LOAD_PAIR5

        uint2* o = yp + ((size_t)b * 2 * RI + 4 * n) * PS2 + (jp + 2);
        o[0] = pack2(__floats2half2_rn(LP0(L0) + SH * HP0(H0), LP0(L1) + SH * HP0(H1)),
                     __floats2half2_rn(SH * (LP0(A0) + HP0(B0)), SH * (LP0(A1) + HP0(B1))));
        o[PS2] = pack2(__floats2half2_rn(LP1(L0) + SH * HP1(H0), LP1(L1) + SH * HP1(H1)),
                       __floats2half2_rn(SH * (LP1(A0) + HP1(B0)), SH * (LP1(A1) + HP1(B1))));
        o[2 * PS2] = pack2(__floats2half2_rn(LP2(L0) + SH * HP2(H0), LP2(L1) + SH * HP2(H1)),
                           __floats2half2_rn(SH * (LP2(A0) + HP2(B0)), SH * (LP2(A1) + HP2(B1))));
        o[3 * PS2] = pack2(__floats2half2_rn(LP3(L0) + SH * HP3(H0), LP3(L1) + SH * HP3(H1)),
                           __floats2half2_rn(SH * (LP3(A0) + HP3(B0)), SH * (LP3(A1) + HP3(B1))));
    } else if (jp < ch) {
        kA_scalar<RI, CI, TZ>(z, yh, yp, b, n, 2 * jp, 2 * jp + 4);
        kA_scalar<RI, CI, TZ>(z, yh, yp, b, n, 2 * jp + 1, 2 * jp + 5);
    } else {
        int hp = jp - ch;
        int pc0 = (hp < 2) ? 2 * hp : (CI + 2 * hp);
#pragma unroll
        for (int s = 0; s < 2; s++) {
            int pc = pc0 + s;
            int jc = refl(pc - 4, CI);
            kA_scalar<RI, CI, TZ>(z, yh, yp, b, n, jc, pc);
        }
    }
}

// ===========================================================================
// kB: branch-free row upsampling, 2 rows/thread, 5 uint2 loads per row.
// ===========================================================================
template <int RO, int CO>
__global__ void __launch_bounds__(256)
kB(const uint2* __restrict__ yp, __half* __restrict__ Z) {
    constexpr int ch = CO / 4;
    constexpr int PS2 = (CO / 2 + 12) / 2;
    constexpr int LCH = ilog2c(ch);
    unsigned idx = blockIdx.x * 256u + threadIdx.x;
    int n = idx & (ch - 1);
    int rp = idx >> LCH;
    int row0 = 2 * rp;

#pragma unroll
    for (int rr = 0; rr < 2; rr++) {
        int row = row0 + rr;
        const uint2* q = yp + (size_t)row * PS2 + n;
        uint2 v0 = __ldg(q), v1 = __ldg(q + 1), v2 = __ldg(q + 2),
              v3 = __ldg(q + 3), v4 = __ldg(q + 4);
        float2 u0 = unpk_lo(v0), u1 = unpk_lo(v1), u2 = unpk_lo(v2),
               u3 = unpk_lo(v3), u4 = unpk_lo(v4);
        float2 w0 = unpk_hi(v0), w1 = unpk_hi(v1), w2 = unpk_hi(v2),
               w3 = unpk_hi(v3), w4 = unpk_hi(v4);
        float L[8], H[8];
        L[0] = u0.x; L[1] = u1.x; L[2] = u2.x; L[3] = u3.x;
        L[4] = u1.y; L[5] = u2.y; L[6] = u3.y; L[7] = u4.y;
        H[0] = w0.x; H[1] = w1.x; H[2] = w2.x; H[3] = w3.x;
        H[4] = w1.y; H[5] = w2.y; H[6] = w3.y; H[7] = w4.y;

        __half2 ha = __floats2half2_rn(LP0(L) + HP0(H), LP1(L) + HP1(H));
        __half2 hb = __floats2half2_rn(LP2(L) + HP2(H), LP3(L) + HP3(H));
        reinterpret_cast<uint2*>(Z + (size_t)row * CO)[n] = pack2(ha, hb);
    }
}

// ===========================================================================
// Scalar final-level column helpers (split), writing 2 rows into smem.
// ===========================================================================
template <int RI, int CI>
__device__ void colfin_s_y1(const __half* __restrict__ z, const float* __restrict__ yh,
                            __half* o, int rs, int b, int m, int jc) {
    constexpr int rh = RI / 2;
    int i0 = 2 * m;
    int pj = jc & 1;
    int o6[6];
    float s1v[6], s2v[6];
    int rr[6];
#pragma unroll
    for (int t = 0; t < 6; t++) {
        int rx = refl(i0 - 2 + t, RI);
        rr[t] = rx;
        int ii = rx >> 1, pi = rx & 1;
        o6[t] = ii * CI + (pi ^ pj);
        s1v[t] = (pi & pj) ? -1.f : 1.f;
        s2v[t] = (pi & (pj ^ 1)) ? -1.f : 1.f;
    }
    const __half* zb = z + (size_t)b * RI * CI + jc;
    const float* yb = yh + (size_t)b * 6 * rh * CI + 2 * (jc >> 1);
    const int sb = rh * CI;
    float zr[4];
#pragma unroll
    for (int t = 0; t < 4; t++) zr[t] = ld1(zb + rr[t + 1] * CI);
    float lr[6];
#pragma unroll
    for (int t = 0; t < 6; t++)
        lr[t] = s1v[t] * __ldg(yb + o6[t]) + s2v[t] * __ldg(yb + 5 * sb + o6[t]);
    o[0]  = __float2half(G0 * (zr[0] + zr[2]) + G1 * zr[1]
          + SH * (Q_E * (lr[0] + lr[4]) + Q_D * (lr[1] + lr[3]) + Q_F * lr[2]));
    o[rs] = __float2half(G0 * (zr[1] + zr[3]) + G1 * zr[2]
          + SH * (Q_E * (lr[1] + lr[5]) + Q_D * (lr[2] + lr[4]) + Q_F * lr[3]));
}

template <int RI, int CI>
__device__ void colfin_s_y2(const float* __restrict__ yh,
                            __half* o, int rs, int b, int m, int jc) {
    constexpr int rh = RI / 2;
    int i0 = 2 * m;
    int pj = jc & 1;
    int o6[6];
    float s1v[6], s2v[6];
#pragma unroll
    for (int t = 0; t < 6; t++) {
        int rx = refl(i0 - 2 + t, RI);
        int ii = rx >> 1, pi = rx & 1;
        o6[t] = ii * CI + (pi ^ pj);
        s1v[t] = (pi & pj) ? -1.f : 1.f;
        s2v[t] = (pi & (pj ^ 1)) ? -1.f : 1.f;
    }
    const float* yb = yh + (size_t)b * 6 * rh * CI + 2 * (jc >> 1);
    const int sb = rh * CI;
    float hlr[6], hhr[6];
#pragma unroll
    for (int t = 0; t < 6; t++) {
        hlr[t] = s1v[t] * __ldg(yb + 2 * sb + o6[t]) + s2v[t] * __ldg(yb + 3 * sb + o6[t]);
        hhr[t] = s1v[t] * __ldg(yb + 1 * sb + o6[t]) + s2v[t] * __ldg(yb + 4 * sb + o6[t]);
    }
    o[0]  = __float2half(SH * (G0 * (hlr[1] + hlr[3]) + G1 * hlr[2]
          + Q_E * (hhr[0] + hhr[4]) + Q_D * (hhr[1] + hhr[3]) + Q_F * hhr[2]));
    o[rs] = __float2half(SH * (G0 * (hlr[2] + hlr[4]) + G1 * hlr[3]
          + Q_E * (hhr[1] + hhr[5]) + Q_D * (hhr[2] + hhr[4]) + Q_F * hhr[3]));
}

// ===========================================================================
// kCDf: fused final level. z:(128,RI,CI), yh0 -> out:(128,RI,CI) fp32.
// Tile: 32 x 32 out. smem y tiles: 32 x 18 half2 (+pad).
// ===========================================================================
template <int RI, int CI>
__global__ void __launch_bounds__(256)
kCDf(const __half* __restrict__ z, const float* __restrict__ yh,
     float* __restrict__ out) {
    constexpr int rh = RI / 2, chb = CI / 2, MP = rh / 2;
    constexpr int SROW = 19;
    __shared__ __half2 y1s[32 * SROW];
    __shared__ __half2 y2s[32 * SROW];
    int b = blockIdx.z;
    int i0 = blockIdx.y * 32;
    int u0 = blockIdx.x * 32;
    int mp0 = i0 >> 2;
    int tid = threadIdx.x;

    const __half2* zb2 = (const __half2*)z + (size_t)b * RI * chb;
    const float2* yb2 = (const float2*)yh + (size_t)b * 6 * rh * chb;
    const int sstr = rh * chb;

#define LOAD_PAIR4(S1, S2, B0, B1)                                            \
    {                                                                         \
        float2 w1[4], w2[4];                                                  \
        _Pragma("unroll") for (int t = 0; t < 4; t++) {                       \
            w1[t] = __ldg(yb2j + ((S1) * sstr + (mm - 1 + t) * chb));         \
            w2[t] = __ldg(yb2j + ((S2) * sstr + (mm - 1 + t) * chb));         \
        }                                                                     \
        _Pragma("unroll") for (int t = 0; t < 4; t++) {                       \
            B0[2 * t] = w1[t].x + w2[t].x;                                    \
            B1[2 * t] = w1[t].y + w2[t].y;                                    \
            B0[2 * t + 1] = w1[t].y - w2[t].y;                                \
            B1[2 * t + 1] = w2[t].x - w1[t].x;                                \
        }                                                                     \
    }

    for (int it = tid; it < 288; it += 256) {
        int isy2 = it >= 144;
        int i2 = it - (isy2 ? 144 : 0);
        int cp = i2 % 18;
        int mp_l = i2 / 18;
        int mp_g = mp0 + mp_l;
        int mm = 2 * mp_g;
        int e = u0 - 2 + 2 * cp;
        if (e >= 0 && e + 1 < CI && mp_g >= 1 && mp_g <= MP - 2) {
            int jj = e >> 1;
            const float2* yb2j = yb2 + jj;
            int i0g = 2 * mm;
            if (!isy2) {
                float2 zr[6];
#pragma unroll
                for (int t = 0; t < 6; t++) zr[t] = ld2(zb2 + jj + (i0g - 1 + t) * chb);
                float lr0[8], lr1[8];
                LOAD_PAIR4(0, 5, lr0, lr1);
                __half2* o = y1s + (4 * mp_l) * SROW + cp;
#pragma unroll
                for (int q = 0; q < 4; q++) {
                    o[q * SROW] = __floats2half2_rn(
                        G0 * (zr[q].x + zr[q + 2].x) + G1 * zr[q + 1].x
                      + SH * (Q_E * (lr0[q] + lr0[q + 4]) + Q_D * (lr0[q + 1] + lr0[q + 3]) + Q_F * lr0[q + 2]),
                        G0 * (zr[q].y + zr[q + 2].y) + G1 * zr[q + 1].y
                      + SH * (Q_E * (lr1[q] + lr1[q + 4]) + Q_D * (lr1[q + 1] + lr1[q + 3]) + Q_F * lr1[q + 2]));
                }
            } else {
                float hl0[8], hl1[8], hh0[8], hh1[8];
                LOAD_PAIR4(2, 3, hl0, hl1);
                LOAD_PAIR4(1, 4, hh0, hh1);
                __half2* o = y2s + (4 * mp_l) * SROW + cp;
#pragma unroll
                for (int q = 0; q < 4; q++) {
                    o[q * SROW] = __floats2half2_rn(
                        SH * (G0 * (hl0[q + 1] + hl0[q + 3]) + G1 * hl0[q + 2]
                      + Q_E * (hh0[q] + hh0[q + 4]) + Q_D * (hh0[q + 1] + hh0[q + 3]) + Q_F * hh0[q + 2]),
                        SH * (G0 * (hl1[q + 1] + hl1[q + 3]) + G1 * hl1[q + 2]
                      + Q_E * (hh1[q] + hh1[q + 4]) + Q_D * (hh1[q + 1] + hh1[q + 3]) + Q_F * hh1[q + 2]));
                }
            }
        } else {
#pragma unroll
            for (int dm = 0; dm < 2; dm++) {
#pragma unroll
                for (int s = 0; s < 2; s++) {
                    int jc = refl(e + s, CI);
                    __half* oh = (__half*)(isy2 ? y2s : y1s)
                               + (4 * mp_l + 2 * dm) * (2 * SROW) + 2 * cp + s;
                    if (!isy2) colfin_s_y1<RI, CI>(z, yh, oh, 2 * SROW, b, mm + dm, jc);
                    else       colfin_s_y2<RI, CI>(yh, oh, 2 * SROW, b, mm + dm, jc);
                }
            }
        }
    }
#undef LOAD_PAIR4
    __syncthreads();

    // -------- phase 2: row filter out of smem, 256 items --------
    {
        int p = tid & 7, i_l = tid >> 3;
        const __half2* q1 = y1s + i_l * SROW + 2 * p;
        const __half2* q2 = y2s + i_l * SROW + 2 * p;
        float2 f0 = __half22float2(q1[0]), f1 = __half22float2(q1[1]),
               f2 = __half22float2(q1[2]), f3 = __half22float2(q1[3]);
        float2 g0 = __half22float2(q2[0]), g1 = __half22float2(q2[1]),
               g2 = __half22float2(q2[2]), g3 = __half22float2(q2[3]);
        float a[6], v[8];
        a[0] = f0.y; a[1] = f1.x; a[2] = f1.y; a[3] = f2.x; a[4] = f2.y; a[5] = f3.x;
        v[0] = g0.x; v[1] = g0.y; v[2] = g1.x; v[3] = g1.y;
        v[4] = g2.x; v[5] = g2.y; v[6] = g3.x; v[7] = g3.y;
        float4 o;
        o.x = G0 * (a[0] + a[2]) + G1 * a[1] + Q_E * (v[0] + v[4]) + Q_D * (v[1] + v[3]) + Q_F * v[2];
        o.y = G0 * (a[1] + a[3]) + G1 * a[2] + Q_E * (v[1] + v[5]) + Q_D * (v[2] + v[4]) + Q_F * v[3];
        o.z = G0 * (a[2] + a[4]) + G1 * a[3] + Q_E * (v[2] + v[6]) + Q_D * (v[3] + v[5]) + Q_F * v[4];
        o.w = G0 * (a[3] + a[5]) + G1 * a[4] + Q_E * (v[3] + v[7]) + Q_D * (v[4] + v[6]) + Q_F * v[5];
        reinterpret_cast<float4*>(out + ((size_t)b * RI + i0 + i_l) * CI + u0)[p] = o;
    }
}

extern "C" void kernel_launch(void* const* d_in, const int* in_sizes, int n_in,
                              void* d_out, int out_size) {
    const float *yl = nullptr, *yh0 = nullptr, *yh1 = nullptr, *yh2 = nullptr;
    for (int i = 0; i < n_in; i++) {
        switch (in_sizes[i]) {
            case 524288:   yl  = (const float*)d_in[i]; break;  // 128*64*64
            case 25165824: yh0 = (const float*)d_in[i]; break;  // 128*6*128*128*2
            case 6291456:  yh1 = (const float*)d_in[i]; break;  // 128*6*64*64*2
            case 1572864:  yh2 = (const float*)d_in[i]; break;  // 128*6*32*32*2
            default: break;
        }
    }

    uint2* pyp;
    __half *pz128, *pz256;
    cudaGetSymbolAddress((void**)&pyp,   g_yp);
    cudaGetSymbolAddress((void**)&pz128, g_z128);
    cudaGetSymbolAddress((void**)&pz256, g_z256);

    // Level 1: (64,64) -> (128,128)
    kA<64, 64, float><<<128 * 32 * 37 / 256, 256>>>(yl, yh2, pyp);
    kB<128, 128><<<128 * 64 * 32 / 256, 256>>>(pyp, pz128);

    // Level 2: (128,128) -> (256,256)
    kA<128, 128, __half><<<128 * 64 * 69 / 256, 256>>>(pz128, yh1, pyp);
    kB<256, 256><<<128 * 128 * 64 / 256, 256>>>(pyp, pz256);

    // Final level: fused col+row -> out
    kCDf<256, 256><<<dim3(8, 8, 128), 256>>>(pz256, yh0, (float*)d_out);
}

// round 13
// speedup vs baseline: 1.1685x; 1.1006x over previous
#include <cuda_runtime.h>
#include <cuda_fp16.h>

// ---------------------------------------------------------------------------
// Inverse DTCWT, 3 levels. R9 structure: split kernels, fp16 intermediates,
// padded + INTERLEAVED y buffer (uint2 = {y1 half2, y2 half2}).
// R13: kB/kD widened to n-pair/p-pair per thread (shared windows, uint4 store).
// ---------------------------------------------------------------------------

#define SH   0.70710678118654752440f
#define C_A  0.23389032f
#define C_B  0.5875183f
#define C_C  0.11430184f
#define C_D  0.76027237f
#define C_E  0.08832942f
#define C_F  0.03516384f

#define G0   0.35355339059327f
#define G1   0.70710678118655f
#define Q_E  (-0.08838834764832f)
#define Q_D  (-0.17677669529664f)
#define Q_F  0.53033008588991f

#define LP0(L) ( C_A*L[1] + C_B*L[2] - C_C*L[3])
#define LP1(L) ( C_D*L[5] - C_E*L[6] + C_F*L[7])
#define LP2(L) ( C_F*L[0] - C_E*L[1] + C_D*L[2])
#define LP3(L) (-C_C*L[4] + C_B*L[5] + C_A*L[6])
#define HP0(H) (-C_D*H[5] + C_E*H[6] - C_F*H[7])
#define HP1(H) ( C_A*H[1] + C_B*H[2] - C_C*H[3])
#define HP2(H) (-C_C*H[4] + C_B*H[5] + C_A*H[6])
#define HP3(H) (-C_F*H[0] + C_E*H[1] - C_D*H[2])

__device__ uint2  g_yp[128 * 256 * 134];
__device__ __half g_z128[128 * 128 * 128];
__device__ __half g_z256[128 * 256 * 256];

__device__ __forceinline__ int refl(int i, int n) {
    i = (i < 0) ? (-1 - i) : i;
    return (i >= n) ? (2 * n - 1 - i) : i;
}

__host__ __device__ constexpr int ilog2c(int v) { return v <= 1 ? 0 : 1 + ilog2c(v >> 1); }

__device__ __forceinline__ float  ld1(const float* p)   { return __ldg(p); }
__device__ __forceinline__ float  ld1(const __half* p)  { return __half2float(__ldg(p)); }
__device__ __forceinline__ float2 ld2(const float2* p)  { return __ldg(p); }
__device__ __forceinline__ float2 ld2(const __half2* p) { return __half22float2(__ldg(p)); }

__device__ __forceinline__ uint2 pack2(__half2 a, __half2 b) {
    uint2 r;
    r.x = *reinterpret_cast<const unsigned*>(&a);
    r.y = *reinterpret_cast<const unsigned*>(&b);
    return r;
}
__device__ __forceinline__ float2 unpk_lo(uint2 v) {
    __half2 h = *reinterpret_cast<const __half2*>(&v.x);
    return __half22float2(h);
}
__device__ __forceinline__ float2 unpk_hi(uint2 v) {
    __half2 h = *reinterpret_cast<const __half2*>(&v.y);
    return __half22float2(h);
}

template <typename T> struct vec2of;
template <> struct vec2of<float>  { using t = float2; };
template <> struct vec2of<__half> { using t = __half2; };

// ===========================================================================
// kA scalar path: writes single halves into interleaved layout.
// ===========================================================================
template <int RI, int CI, typename TZ>
__device__ void kA_scalar(const TZ* __restrict__ z, const float* __restrict__ yh,
                          uint2* __restrict__ yp, int b, int n, int jc, int pc) {
    constexpr int rh = RI / 2, PS2 = (CI + 12) / 2;
    const int d8[8] = {-4, -2, 0, 2, -1, 1, 3, 5};
    int pj = jc & 1;
    int rw[8], oB[8];
    float s1v[8], s2v[8];
#pragma unroll
    for (int t = 0; t < 8; t++) {
        int rr = refl(2 * n + d8[t], RI);
        rw[t] = rr;
        int ii = rr >> 1, pi = rr & 1;
        oB[t] = ii * CI + (pi ^ pj);
        s1v[t] = (pi & pj) ? -1.f : 1.f;
        s2v[t] = (pi & (pj ^ 1)) ? -1.f : 1.f;
    }
    const TZ* zb = z + (size_t)b * RI * CI + jc;
    const float* yb = yh + (size_t)b * 6 * rh * CI + 2 * (jc >> 1);
    const int sb = rh * CI;

    float L[8], H[8], A[8], B[8];
#pragma unroll
    for (int t = 0; t < 8; t++) L[t] = ld1(zb + rw[t] * CI);
#pragma unroll
    for (int t = 0; t < 8; t++) {
        H[t] = s1v[t] * __ldg(yb + oB[t]) + s2v[t] * __ldg(yb + 5 * sb + oB[t]);          // lh
        A[t] = s1v[t] * __ldg(yb + 2 * sb + oB[t]) + s2v[t] * __ldg(yb + 3 * sb + oB[t]); // hl
        B[t] = s1v[t] * __ldg(yb + 1 * sb + oB[t]) + s2v[t] * __ldg(yb + 4 * sb + oB[t]); // hh
    }

    __half* o = (__half*)yp + (((size_t)b * 2 * RI + 4 * n) * PS2 + (pc >> 1)) * 4 + (pc & 1);
    const int rs = PS2 * 4;
    o[0]          = __float2half(LP0(L) + SH * HP0(H));
    o[2]          = __float2half(SH * (LP0(A) + HP0(B)));
    o[rs]         = __float2half(LP1(L) + SH * HP1(H));
    o[rs + 2]     = __float2half(SH * (LP1(A) + HP1(B)));
    o[2 * rs]     = __float2half(LP2(L) + SH * HP2(H));
    o[2 * rs + 2] = __float2half(SH * (LP2(A) + HP2(B)));
    o[3 * rs]     = __float2half(LP3(L) + SH * HP3(H));
    o[3 * rs + 2] = __float2half(SH * (LP3(A) + HP3(B)));
}

// ===========================================================================
// kA: column upsampling -> interleaved padded buffer, cols 4..CI+9.
// ===========================================================================
template <int RI, int CI, typename TZ>
__global__ void __launch_bounds__(256)
kA(const TZ* __restrict__ z, const float* __restrict__ yh,
   uint2* __restrict__ yp) {
    constexpr int rh = RI / 2, ch = CI / 2, JP = ch + 5, PS2 = (CI + 12) / 2;
    using TZ2 = typename vec2of<TZ>::t;
    unsigned idx = blockIdx.x * 256u + threadIdx.x;
    int jp = idx % JP;
    int n = (idx / JP) % rh;
    int b = idx / (JP * rh);

    if (jp < ch && n >= 2 && n <= rh - 3) {
        const TZ2* z2 = (const TZ2*)z + (size_t)b * RI * ch + jp;
        const float2* yb2 = (const float2*)yh + (size_t)b * 6 * rh * ch + jp;
        const int sstr = rh * ch;
        int base = 2 * n;

        float2 Lz[8];
        Lz[0] = ld2(z2 + (base - 4) * ch);
        Lz[1] = ld2(z2 + (base - 2) * ch);
        Lz[2] = ld2(z2 + base * ch);
        Lz[3] = ld2(z2 + (base + 2) * ch);
        Lz[4] = ld2(z2 + (base - 1) * ch);
        Lz[5] = ld2(z2 + (base + 1) * ch);
        Lz[6] = ld2(z2 + (base + 3) * ch);
        Lz[7] = ld2(z2 + (base + 5) * ch);
        float L0[8], L1[8];
#pragma unroll
        for (int t = 0; t < 8; t++) { L0[t] = Lz[t].x; L1[t] = Lz[t].y; }

#define LOAD_PAIR5(S1, S2, B0, B1)                                            \
    {                                                                         \
        float2 w1[5], w2[5];                                                  \
        _Pragma("unroll") for (int t = 0; t < 5; t++) {                       \
            w1[t] = __ldg(yb2 + ((S1) * sstr + (n - 2 + t) * ch));            \
            w2[t] = __ldg(yb2 + ((S2) * sstr + (n - 2 + t) * ch));            \
        }                                                                     \
        _Pragma("unroll") for (int t = 0; t < 4; t++) {                       \
            B0[t] = w1[t].x + w2[t].x;                                        \
            B1[t] = w1[t].y + w2[t].y;                                        \
            B0[4 + t] = w1[t + 1].y - w2[t + 1].y;                            \
            B1[4 + t] = w2[t + 1].x - w1[t + 1].x;                            \
        }                                                                     \
    }
        float H0[8], H1[8], A0[8], A1[8], B0[8], B1[8];
        LOAD_PAIR5(0, 5, H0, H1);  // lh
        LOAD_PAIR5(2, 3, A0, A1);  // hl
        LOAD_PAIR5(1, 4, B0, B1);  // hh
#undef LOAD_PAIR5

        uint2* o = yp + ((size_t)b * 2 * RI + 4 * n) * PS2 + (jp + 2);
        o[0] = pack2(__floats2half2_rn(LP0(L0) + SH * HP0(H0), LP0(L1) + SH * HP0(H1)),
                     __floats2half2_rn(SH * (LP0(A0) + HP0(B0)), SH * (LP0(A1) + HP0(B1))));
        o[PS2] = pack2(__floats2half2_rn(LP1(L0) + SH * HP1(H0), LP1(L1) + SH * HP1(H1)),
                       __floats2half2_rn(SH * (LP1(A0) + HP1(B0)), SH * (LP1(A1) + HP1(B1))));
        o[2 * PS2] = pack2(__floats2half2_rn(LP2(L0) + SH * HP2(H0), LP2(L1) + SH * HP2(H1)),
                           __floats2half2_rn(SH * (LP2(A0) + HP2(B0)), SH * (LP2(A1) + HP2(B1))));
        o[3 * PS2] = pack2(__floats2half2_rn(LP3(L0) + SH * HP3(H0), LP3(L1) + SH * HP3(H1)),
                           __floats2half2_rn(SH * (LP3(A0) + HP3(B0)), SH * (LP3(A1) + HP3(B1))));
    } else if (jp < ch) {
        kA_scalar<RI, CI, TZ>(z, yh, yp, b, n, 2 * jp, 2 * jp + 4);
        kA_scalar<RI, CI, TZ>(z, yh, yp, b, n, 2 * jp + 1, 2 * jp + 5);
    } else {
        int hp = jp - ch;
        int pc0 = (hp < 2) ? 2 * hp : (CI + 2 * hp);
#pragma unroll
        for (int s = 0; s < 2; s++) {
            int pc = pc0 + s;
            int jc = refl(pc - 4, CI);
            kA_scalar<RI, CI, TZ>(z, yh, yp, b, n, jc, pc);
        }
    }
}

// ===========================================================================
// kB: branch-free row upsampling, 2 rows x n-PAIR per thread.
// Per row: 6 uint2 loads -> 8 output cols -> one uint4 store.
// ===========================================================================
template <int RO, int CO>
__global__ void __launch_bounds__(256)
kB(const uint2* __restrict__ yp, __half* __restrict__ Z) {
    constexpr int ch = CO / 4;               // # of n positions
    constexpr int NP = ch / 2;               // n-pairs
    constexpr int PS2 = (CO / 2 + 12) / 2;
    constexpr int LNP = ilog2c(NP);
    unsigned idx = blockIdx.x * 256u + threadIdx.x;
    int np = idx & (NP - 1);
    int rp = idx >> LNP;
    int row0 = 2 * rp;
    int n0 = 2 * np;

#pragma unroll
    for (int rr = 0; rr < 2; rr++) {
        int row = row0 + rr;
        const uint2* q = yp + (size_t)row * PS2 + n0;
        uint2 v0 = __ldg(q), v1 = __ldg(q + 1), v2 = __ldg(q + 2),
              v3 = __ldg(q + 3), v4 = __ldg(q + 4), v5 = __ldg(q + 5);
        float2 u0 = unpk_lo(v0), u1 = unpk_lo(v1), u2 = unpk_lo(v2),
               u3 = unpk_lo(v3), u4 = unpk_lo(v4), u5 = unpk_lo(v5);
        float2 w0 = unpk_hi(v0), w1 = unpk_hi(v1), w2 = unpk_hi(v2),
               w3 = unpk_hi(v3), w4 = unpk_hi(v4), w5 = unpk_hi(v5);

        float L[8], H[8];
        // n = n0
        L[0] = u0.x; L[1] = u1.x; L[2] = u2.x; L[3] = u3.x;
        L[4] = u1.y; L[5] = u2.y; L[6] = u3.y; L[7] = u4.y;
        H[0] = w0.x; H[1] = w1.x; H[2] = w2.x; H[3] = w3.x;
        H[4] = w1.y; H[5] = w2.y; H[6] = w3.y; H[7] = w4.y;
        __half2 ha0 = __floats2half2_rn(LP0(L) + HP0(H), LP1(L) + HP1(H));
        __half2 hb0 = __floats2half2_rn(LP2(L) + HP2(H), LP3(L) + HP3(H));
        // n = n0 + 1 (window shifted by one uint2)
        L[0] = u1.x; L[1] = u2.x; L[2] = u3.x; L[3] = u4.x;
        L[4] = u2.y; L[5] = u3.y; L[6] = u4.y; L[7] = u5.y;
        H[0] = w1.x; H[1] = w2.x; H[2] = w3.x; H[3] = w4.x;
        H[4] = w2.y; H[5] = w3.y; H[6] = w4.y; H[7] = w5.y;
        __half2 ha1 = __floats2half2_rn(LP0(L) + HP0(H), LP1(L) + HP1(H));
        __half2 hb1 = __floats2half2_rn(LP2(L) + HP2(H), LP3(L) + HP3(H));

        uint4 pk;
        pk.x = *reinterpret_cast<const unsigned*>(&ha0);
        pk.y = *reinterpret_cast<const unsigned*>(&hb0);
        pk.z = *reinterpret_cast<const unsigned*>(&ha1);
        pk.w = *reinterpret_cast<const unsigned*>(&hb1);
        reinterpret_cast<uint4*>(Z + (size_t)row * CO)[np] = pk;
    }
}

// ===========================================================================
// kC scalar path.
// ===========================================================================
template <int RI, int CI>
__device__ void kC_scalar(const __half* __restrict__ z, const float* __restrict__ yh,
                          uint2* __restrict__ yp, int b, int m, int jc, int pc) {
    constexpr int rh = RI / 2, PS2 = (CI + 10) / 2;
    int i0 = 2 * m;
    int pj = jc & 1;
    int o6[6];
    float s1v[6], s2v[6];
    int rr[6];
#pragma unroll
    for (int t = 0; t < 6; t++) {
        int rx = refl(i0 - 2 + t, RI);
        rr[t] = rx;
        int ii = rx >> 1, pi = rx & 1;
        o6[t] = ii * CI + (pi ^ pj);
        s1v[t] = (pi & pj) ? -1.f : 1.f;
        s2v[t] = (pi & (pj ^ 1)) ? -1.f : 1.f;
    }
    const __half* zb = z + (size_t)b * RI * CI + jc;
    const float* yb = yh + (size_t)b * 6 * rh * CI + 2 * (jc >> 1);
    const int sb = rh * CI;

    float zr[4];
#pragma unroll
    for (int t = 0; t < 4; t++) zr[t] = ld1(zb + rr[t + 1] * CI);

    float lr[6], hlr[6], hhr[6];
#pragma unroll
    for (int t = 0; t < 6; t++) {
        lr[t]  = s1v[t] * __ldg(yb + o6[t])          + s2v[t] * __ldg(yb + 5 * sb + o6[t]);
        hlr[t] = s1v[t] * __ldg(yb + 2 * sb + o6[t]) + s2v[t] * __ldg(yb + 3 * sb + o6[t]);
        hhr[t] = s1v[t] * __ldg(yb + 1 * sb + o6[t]) + s2v[t] * __ldg(yb + 4 * sb + o6[t]);
    }
    __half* o = (__half*)yp + (((size_t)b * RI + i0) * PS2 + (pc >> 1)) * 4 + (pc & 1);
    const int rs = PS2 * 4;
    o[0]      = __float2half(G0 * (zr[0] + zr[2]) + G1 * zr[1]
              + SH * (Q_E * (lr[0] + lr[4]) + Q_D * (lr[1] + lr[3]) + Q_F * lr[2]));
    o[rs]     = __float2half(G0 * (zr[1] + zr[3]) + G1 * zr[2]
              + SH * (Q_E * (lr[1] + lr[5]) + Q_D * (lr[2] + lr[4]) + Q_F * lr[3]));
    o[2]      = __float2half(SH * (G0 * (hlr[1] + hlr[3]) + G1 * hlr[2]
              + Q_E * (hhr[0] + hhr[4]) + Q_D * (hhr[1] + hhr[3]) + Q_F * hhr[2]));
    o[rs + 2] = __float2half(SH * (G0 * (hlr[2] + hlr[4]) + G1 * hlr[3]
              + Q_E * (hhr[1] + hhr[5]) + Q_D * (hhr[2] + hhr[4]) + Q_F * hhr[3]));
}

// ===========================================================================
// kC: final-level column filters, m-pair per thread (4 output rows).
// ===========================================================================
template <int RI, int CI>
__global__ void __launch_bounds__(256)
kC(const __half* __restrict__ z, const float* __restrict__ yh,
   uint2* __restrict__ yp) {
    constexpr int rh = RI / 2, chb = CI / 2, JP = chb + 5, PS2 = (CI + 10) / 2;
    constexpr int MP = rh / 2;
    unsigned idx = blockIdx.x * 256u + threadIdx.x;
    int jp = idx % JP;
    int mp = (idx / JP) % MP;
    int b = idx / (JP * MP);
    int mm = 2 * mp;

    if (jp < chb && mp >= 1 && mp <= MP - 2) {
        int i0 = 2 * mm;
        const __half2* z2 = (const __half2*)z + (size_t)b * RI * chb + jp;
        const float2* yb2 = (const float2*)yh + (size_t)b * 6 * rh * chb + jp;
        const int sstr = rh * chb;

        float2 zr[6];
#pragma unroll
        for (int t = 0; t < 6; t++) zr[t] = ld2(z2 + (i0 - 1 + t) * chb);

#define LOAD_PAIR4(S1, S2, B0, B1)                                            \
    {                                                                         \
        float2 w1[4], w2[4];                                                  \
        _Pragma("unroll") for (int t = 0; t < 4; t++) {                       \
            w1[t] = __ldg(yb2 + ((S1) * sstr + (mm - 1 + t) * chb));          \
            w2[t] = __ldg(yb2 + ((S2) * sstr + (mm - 1 + t) * chb));          \
        }                                                                     \
        _Pragma("unroll") for (int t = 0; t < 4; t++) {                       \
            B0[2 * t] = w1[t].x + w2[t].x;                                    \
            B1[2 * t] = w1[t].y + w2[t].y;                                    \
            B0[2 * t + 1] = w1[t].y - w2[t].y;                                \
            B1[2 * t + 1] = w2[t].x - w1[t].x;                                \
        }                                                                     \
    }
        float lr0[8], lr1[8], hl0[8], hl1[8], hh0[8], hh1[8];
        LOAD_PAIR4(0, 5, lr0, lr1);
        LOAD_PAIR4(2, 3, hl0, hl1);
        LOAD_PAIR4(1, 4, hh0, hh1);
#undef LOAD_PAIR4

        uint2* o = yp + ((size_t)b * RI + i0) * PS2 + (jp + 2);
#pragma unroll
        for (int q = 0; q < 4; q++) {
            __half2 h1 = __floats2half2_rn(
                G0 * (zr[q].x + zr[q + 2].x) + G1 * zr[q + 1].x
              + SH * (Q_E * (lr0[q] + lr0[q + 4]) + Q_D * (lr0[q + 1] + lr0[q + 3]) + Q_F * lr0[q + 2]),
                G0 * (zr[q].y + zr[q + 2].y) + G1 * zr[q + 1].y
              + SH * (Q_E * (lr1[q] + lr1[q + 4]) + Q_D * (lr1[q + 1] + lr1[q + 3]) + Q_F * lr1[q + 2]));
            __half2 h2 = __floats2half2_rn(
                SH * (G0 * (hl0[q + 1] + hl0[q + 3]) + G1 * hl0[q + 2]
              + Q_E * (hh0[q] + hh0[q + 4]) + Q_D * (hh0[q + 1] + hh0[q + 3]) + Q_F * hh0[q + 2]),
                SH * (G0 * (hl1[q + 1] + hl1[q + 3]) + G1 * hl1[q + 2]
              + Q_E * (hh1[q] + hh1[q + 4]) + Q_D * (hh1[q + 1] + hh1[q + 3]) + Q_F * hh1[q + 2]));
            o[q * PS2] = pack2(h1, h2);
        }
    } else if (jp < chb) {
#pragma unroll
        for (int dm = 0; dm < 2; dm++) {
            kC_scalar<RI, CI>(z, yh, yp, b, mm + dm, 2 * jp, 2 * jp + 4);
            kC_scalar<RI, CI>(z, yh, yp, b, mm + dm, 2 * jp + 1, 2 * jp + 5);
        }
    } else {
        int hp = jp - chb;
        int pc0 = (hp < 2) ? 2 * hp : (CI + 2 * hp);
#pragma unroll
        for (int dm = 0; dm < 2; dm++) {
#pragma unroll
            for (int s = 0; s < 2; s++) {
                int pc = pc0 + s;
                int jc = refl(pc - 4, CI);
                kC_scalar<RI, CI>(z, yh, yp, b, mm + dm, jc, pc);
            }
        }
    }
}

// ===========================================================================
// kD: branch-free final row filters, 2 rows x p-PAIR per thread.
// Per row: 6 uint2 loads -> 8 output cols -> two float4 stores.
// ===========================================================================
template <int R, int C>
__global__ void __launch_bounds__(256)
kD(const uint2* __restrict__ yp, float* __restrict__ out) {
    constexpr int P = C / 4, PP = P / 2, PS2 = (C + 10) / 2;
    constexpr int LPP = ilog2c(PP);
    unsigned idx = blockIdx.x * 256u + threadIdx.x;
    int pp = idx & (PP - 1);
    int rp = idx >> LPP;
    int row0 = 2 * rp;

#pragma unroll
    for (int rr = 0; rr < 2; rr++) {
        int row = row0 + rr;
        const uint2* q = yp + (size_t)row * PS2 + (4 * pp + 1);
        uint2 v0 = __ldg(q), v1 = __ldg(q + 1), v2 = __ldg(q + 2),
              v3 = __ldg(q + 3), v4 = __ldg(q + 4), v5 = __ldg(q + 5);
        float2 f0 = unpk_lo(v0), f1 = unpk_lo(v1), f2 = unpk_lo(v2),
               f3 = unpk_lo(v3), f4 = unpk_lo(v4), f5 = unpk_lo(v5);
        float2 g0 = unpk_hi(v0), g1 = unpk_hi(v1), g2 = unpk_hi(v2),
               g3 = unpk_hi(v3), g4 = unpk_hi(v4), g5 = unpk_hi(v5);

        float a[6], v[8];
        // p = 2*pp
        a[0] = f0.y; a[1] = f1.x; a[2] = f1.y; a[3] = f2.x; a[4] = f2.y; a[5] = f3.x;
        v[0] = g0.x; v[1] = g0.y; v[2] = g1.x; v[3] = g1.y;
        v[4] = g2.x; v[5] = g2.y; v[6] = g3.x; v[7] = g3.y;
        float4 o0;
        o0.x = G0 * (a[0] + a[2]) + G1 * a[1] + Q_E * (v[0] + v[4]) + Q_D * (v[1] + v[3]) + Q_F * v[2];
        o0.y = G0 * (a[1] + a[3]) + G1 * a[2] + Q_E * (v[1] + v[5]) + Q_D * (v[2] + v[4]) + Q_F * v[3];
        o0.z = G0 * (a[2] + a[4]) + G1 * a[3] + Q_E * (v[2] + v[6]) + Q_D * (v[3] + v[5]) + Q_F * v[4];
        o0.w = G0 * (a[3] + a[5]) + G1 * a[4] + Q_E * (v[3] + v[7]) + Q_D * (v[4] + v[6]) + Q_F * v[5];
        // p = 2*pp + 1 (shift window by 2 uint2)
        a[0] = f2.y; a[1] = f3.x; a[2] = f3.y; a[3] = f4.x; a[4] = f4.y; a[5] = f5.x;
        v[0] = g2.x; v[1] = g2.y; v[2] = g3.x; v[3] = g3.y;
        v[4] = g4.x; v[5] = g4.y; v[6] = g5.x; v[7] = g5.y;
        float4 o1;
        o1.x = G0 * (a[0] + a[2]) + G1 * a[1] + Q_E * (v[0] + v[4]) + Q_D * (v[1] + v[3]) + Q_F * v[2];
        o1.y = G0 * (a[1] + a[3]) + G1 * a[2] + Q_E * (v[1] + v[5]) + Q_D * (v[2] + v[4]) + Q_F * v[3];
        o1.z = G0 * (a[2] + a[4]) + G1 * a[3] + Q_E * (v[2] + v[6]) + Q_D * (v[3] + v[5]) + Q_F * v[4];
        o1.w = G0 * (a[3] + a[5]) + G1 * a[4] + Q_E * (v[3] + v[7]) + Q_D * (v[4] + v[6]) + Q_F * v[5];

        float4* ob = reinterpret_cast<float4*>(out + (size_t)row * C);
        ob[2 * pp]     = o0;
        ob[2 * pp + 1] = o1;
    }
}

extern "C" void kernel_launch(void* const* d_in, const int* in_sizes, int n_in,
                              void* d_out, int out_size) {
    const float *yl = nullptr, *yh0 = nullptr, *yh1 = nullptr, *yh2 = nullptr;
    for (int i = 0; i < n_in; i++) {
        switch (in_sizes[i]) {
            case 524288:   yl  = (const float*)d_in[i]; break;  // 128*64*64
            case 25165824: yh0 = (const float*)d_in[i]; break;  // 128*6*128*128*2
            case 6291456:  yh1 = (const float*)d_in[i]; break;  // 128*6*64*64*2
            case 1572864:  yh2 = (const float*)d_in[i]; break;  // 128*6*32*32*2
            default: break;
        }
    }

    uint2* pyp;
    __half *pz128, *pz256;
    cudaGetSymbolAddress((void**)&pyp,   g_yp);
    cudaGetSymbolAddress((void**)&pz128, g_z128);
    cudaGetSymbolAddress((void**)&pz256, g_z256);

    // Level 1: (64,64) -> (128,128)
    kA<64, 64, float><<<128 * 32 * 37 / 256, 256>>>(yl, yh2, pyp);
    kB<128, 128><<<128 * 64 * 16 / 256, 256>>>(pyp, pz128);

    // Level 2: (128,128) -> (256,256)
    kA<128, 128, __half><<<128 * 64 * 69 / 256, 256>>>(pz128, yh1, pyp);
    kB<256, 256><<<128 * 128 * 32 / 256, 256>>>(pyp, pz256);

    // Final level
    kC<256, 256><<<128 * 64 * 133 / 256, 256>>>(pz256, yh0, pyp);
    kD<256, 256><<<128 * 128 * 32 / 256, 256>>>(pyp, (float*)d_out);
}

// round 14
// speedup vs baseline: 1.2497x; 1.0695x over previous
#include <cuda_runtime.h>
#include <cuda_fp16.h>

// ---------------------------------------------------------------------------
// Inverse DTCWT, 3 levels. R9 structure (split kernels, fp16 intermediates,
// interleaved padded y buffer). R14: kA widened to n-PAIR per thread.
// ---------------------------------------------------------------------------

#define SH   0.70710678118654752440f
#define C_A  0.23389032f
#define C_B  0.5875183f
#define C_C  0.11430184f
#define C_D  0.76027237f
#define C_E  0.08832942f
#define C_F  0.03516384f

#define G0   0.35355339059327f
#define G1   0.70710678118655f
#define Q_E  (-0.08838834764832f)
#define Q_D  (-0.17677669529664f)
#define Q_F  0.53033008588991f

#define LP0(L) ( C_A*L[1] + C_B*L[2] - C_C*L[3])
#define LP1(L) ( C_D*L[5] - C_E*L[6] + C_F*L[7])
#define LP2(L) ( C_F*L[0] - C_E*L[1] + C_D*L[2])
#define LP3(L) (-C_C*L[4] + C_B*L[5] + C_A*L[6])
#define HP0(H) (-C_D*H[5] + C_E*H[6] - C_F*H[7])
#define HP1(H) ( C_A*H[1] + C_B*H[2] - C_C*H[3])
#define HP2(H) (-C_C*H[4] + C_B*H[5] + C_A*H[6])
#define HP3(H) (-C_F*H[0] + C_E*H[1] - C_D*H[2])

__device__ uint2  g_yp[128 * 256 * 134];
__device__ __half g_z128[128 * 128 * 128];
__device__ __half g_z256[128 * 256 * 256];

__device__ __forceinline__ int refl(int i, int n) {
    i = (i < 0) ? (-1 - i) : i;
    return (i >= n) ? (2 * n - 1 - i) : i;
}

__host__ __device__ constexpr int ilog2c(int v) { return v <= 1 ? 0 : 1 + ilog2c(v >> 1); }

__device__ __forceinline__ float  ld1(const float* p)   { return __ldg(p); }
__device__ __forceinline__ float  ld1(const __half* p)  { return __half2float(__ldg(p)); }
__device__ __forceinline__ float2 ld2(const float2* p)  { return __ldg(p); }
__device__ __forceinline__ float2 ld2(const __half2* p) { return __half22float2(__ldg(p)); }

__device__ __forceinline__ uint2 pack2(__half2 a, __half2 b) {
    uint2 r;
    r.x = *reinterpret_cast<const unsigned*>(&a);
    r.y = *reinterpret_cast<const unsigned*>(&b);
    return r;
}
__device__ __forceinline__ float2 unpk_lo(uint2 v) {
    __half2 h = *reinterpret_cast<const __half2*>(&v.x);
    return __half22float2(h);
}
__device__ __forceinline__ float2 unpk_hi(uint2 v) {
    __half2 h = *reinterpret_cast<const __half2*>(&v.y);
    return __half22float2(h);
}

template <typename T> struct vec2of;
template <> struct vec2of<float>  { using t = float2; };
template <> struct vec2of<__half> { using t = __half2; };

// ===========================================================================
// kA scalar path (single n, single col) — unchanged from R9.
// ===========================================================================
template <int RI, int CI, typename TZ>
__device__ void kA_scalar(const TZ* __restrict__ z, const float* __restrict__ yh,
                          uint2* __restrict__ yp, int b, int n, int jc, int pc) {
    constexpr int rh = RI / 2, PS2 = (CI + 12) / 2;
    const int d8[8] = {-4, -2, 0, 2, -1, 1, 3, 5};
    int pj = jc & 1;
    int rw[8], oB[8];
    float s1v[8], s2v[8];
#pragma unroll
    for (int t = 0; t < 8; t++) {
        int rr = refl(2 * n + d8[t], RI);
        rw[t] = rr;
        int ii = rr >> 1, pi = rr & 1;
        oB[t] = ii * CI + (pi ^ pj);
        s1v[t] = (pi & pj) ? -1.f : 1.f;
        s2v[t] = (pi & (pj ^ 1)) ? -1.f : 1.f;
    }
    const TZ* zb = z + (size_t)b * RI * CI + jc;
    const float* yb = yh + (size_t)b * 6 * rh * CI + 2 * (jc >> 1);
    const int sb = rh * CI;

    float L[8], H[8], A[8], B[8];
#pragma unroll
    for (int t = 0; t < 8; t++) L[t] = ld1(zb + rw[t] * CI);
#pragma unroll
    for (int t = 0; t < 8; t++) {
        H[t] = s1v[t] * __ldg(yb + oB[t]) + s2v[t] * __ldg(yb + 5 * sb + oB[t]);          // lh
        A[t] = s1v[t] * __ldg(yb + 2 * sb + oB[t]) + s2v[t] * __ldg(yb + 3 * sb + oB[t]); // hl
        B[t] = s1v[t] * __ldg(yb + 1 * sb + oB[t]) + s2v[t] * __ldg(yb + 4 * sb + oB[t]); // hh
    }

    __half* o = (__half*)yp + (((size_t)b * 2 * RI + 4 * n) * PS2 + (pc >> 1)) * 4 + (pc & 1);
    const int rs = PS2 * 4;
    o[0]          = __float2half(LP0(L) + SH * HP0(H));
    o[2]          = __float2half(SH * (LP0(A) + HP0(B)));
    o[rs]         = __float2half(LP1(L) + SH * HP1(H));
    o[rs + 2]     = __float2half(SH * (LP1(A) + HP1(B)));
    o[2 * rs]     = __float2half(LP2(L) + SH * HP2(H));
    o[2 * rs + 2] = __float2half(SH * (LP2(A) + HP2(B)));
    o[3 * rs]     = __float2half(LP3(L) + SH * HP3(H));
    o[3 * rs + 2] = __float2half(SH * (LP3(A) + HP3(B)));
}

// ===========================================================================
// kA: column upsampling, n-PAIR per thread. Windows shared between n, n+1:
//   z evens rows 2n+{-4..4 step2} (ze[5]), odds 2n+{-1..7 step2} (zo[5]);
//   subband rows n-2..n+3 (6) -> E[0..4] (rows n-2+t), O[0..4] (rows n-1+t).
// Output n uses index r=0 (E/O/ze/zo[0..3]); n+1 uses r=1 ([1..4]).
// ===========================================================================
template <int RI, int CI, typename TZ>
__global__ void __launch_bounds__(256)
kA(const TZ* __restrict__ z, const float* __restrict__ yh,
   uint2* __restrict__ yp) {
    constexpr int rh = RI / 2, ch = CI / 2, JP = ch + 5, PS2 = (CI + 12) / 2;
    constexpr int NPH = rh / 2;
    using TZ2 = typename vec2of<TZ>::t;
    unsigned idx = blockIdx.x * 256u + threadIdx.x;
    int jp = idx % JP;
    int np = (idx / JP) % NPH;
    int b = idx / (JP * NPH);
    int n = 2 * np;

    if (jp < ch && np >= 1 && np <= NPH - 2) {
        const TZ2* z2 = (const TZ2*)z + (size_t)b * RI * ch + jp;
        const float2* yb2 = (const float2*)yh + (size_t)b * 6 * rh * ch + jp;
        const int sstr = rh * ch;
        int base = 2 * n;

        __half2 y1h[8];

        // ---------- y1 = ifilt_lp(z) + SH * ifilt_hp(lh) ----------
        {
            float2 ze[5], zo[5];
#pragma unroll
            for (int t = 0; t < 5; t++) {
                ze[t] = ld2(z2 + (base - 4 + 2 * t) * ch);
                zo[t] = ld2(z2 + (base - 1 + 2 * t) * ch);
            }
            float E0[5], E1[5], O0[5], O1[5];
            {
                float2 w1[6], w2[6];
#pragma unroll
                for (int t = 0; t < 6; t++) {
                    w1[t] = __ldg(yb2 + (0 * sstr + (n - 2 + t) * ch));
                    w2[t] = __ldg(yb2 + (5 * sstr + (n - 2 + t) * ch));
                }
#pragma unroll
                for (int t = 0; t < 5; t++) {
                    E0[t] = w1[t].x + w2[t].x;
                    E1[t] = w1[t].y + w2[t].y;
                    O0[t] = w1[t + 1].y - w2[t + 1].y;
                    O1[t] = w2[t + 1].x - w1[t + 1].x;
                }
            }
#pragma unroll
            for (int r = 0; r < 2; r++) {
                float L0[8], L1[8], H0[8], H1[8];
#pragma unroll
                for (int t = 0; t < 4; t++) {
                    L0[t] = ze[r + t].x; L1[t] = ze[r + t].y;
                    L0[4 + t] = zo[r + t].x; L1[4 + t] = zo[r + t].y;
                    H0[t] = E0[r + t]; H1[t] = E1[r + t];
                    H0[4 + t] = O0[r + t]; H1[4 + t] = O1[r + t];
                }
                y1h[4 * r + 0] = __floats2half2_rn(LP0(L0) + SH * HP0(H0), LP0(L1) + SH * HP0(H1));
                y1h[4 * r + 1] = __floats2half2_rn(LP1(L0) + SH * HP1(H0), LP1(L1) + SH * HP1(H1));
                y1h[4 * r + 2] = __floats2half2_rn(LP2(L0) + SH * HP2(H0), LP2(L1) + SH * HP2(H1));
                y1h[4 * r + 3] = __floats2half2_rn(LP3(L0) + SH * HP3(H0), LP3(L1) + SH * HP3(H1));
            }
        }

        // ---------- y2 = SH * (ifilt_lp(hl) + ifilt_hp(hh)) ----------
        uint2* o = yp + ((size_t)b * 2 * RI + 4 * n) * PS2 + (jp + 2);
        {
            float AE0[5], AE1[5], AO0[5], AO1[5];  // hl
            float BE0[5], BE1[5], BO0[5], BO1[5];  // hh
            {
                float2 w1[6], w2[6];
#pragma unroll
                for (int t = 0; t < 6; t++) {
                    w1[t] = __ldg(yb2 + (2 * sstr + (n - 2 + t) * ch));
                    w2[t] = __ldg(yb2 + (3 * sstr + (n - 2 + t) * ch));
                }
#pragma unroll
                for (int t = 0; t < 5; t++) {
                    AE0[t] = w1[t].x + w2[t].x;
                    AE1[t] = w1[t].y + w2[t].y;
                    AO0[t] = w1[t + 1].y - w2[t + 1].y;
                    AO1[t] = w2[t + 1].x - w1[t + 1].x;
                }
            }
            {
                float2 w1[6], w2[6];
#pragma unroll
                for (int t = 0; t < 6; t++) {
                    w1[t] = __ldg(yb2 + (1 * sstr + (n - 2 + t) * ch));
                    w2[t] = __ldg(yb2 + (4 * sstr + (n - 2 + t) * ch));
                }
#pragma unroll
                for (int t = 0; t < 5; t++) {
                    BE0[t] = w1[t].x + w2[t].x;
                    BE1[t] = w1[t].y + w2[t].y;
                    BO0[t] = w1[t + 1].y - w2[t + 1].y;
                    BO1[t] = w2[t + 1].x - w1[t + 1].x;
                }
            }
#pragma unroll
            for (int r = 0; r < 2; r++) {
                float A0[8], A1[8], B0[8], B1[8];
#pragma unroll
                for (int t = 0; t < 4; t++) {
                    A0[t] = AE0[r + t]; A1[t] = AE1[r + t];
                    A0[4 + t] = AO0[r + t]; A1[4 + t] = AO1[r + t];
                    B0[t] = BE0[r + t]; B1[t] = BE1[r + t];
                    B0[4 + t] = BO0[r + t]; B1[4 + t] = BO1[r + t];
                }
                __half2 h0 = __floats2half2_rn(SH * (LP0(A0) + HP0(B0)), SH * (LP0(A1) + HP0(B1)));
                __half2 h1 = __floats2half2_rn(SH * (LP1(A0) + HP1(B0)), SH * (LP1(A1) + HP1(B1)));
                __half2 h2 = __floats2half2_rn(SH * (LP2(A0) + HP2(B0)), SH * (LP2(A1) + HP2(B1)));
                __half2 h3 = __floats2half2_rn(SH * (LP3(A0) + HP3(B0)), SH * (LP3(A1) + HP3(B1)));
                o[(4 * r + 0) * PS2] = pack2(y1h[4 * r + 0], h0);
                o[(4 * r + 1) * PS2] = pack2(y1h[4 * r + 1], h1);
                o[(4 * r + 2) * PS2] = pack2(y1h[4 * r + 2], h2);
                o[(4 * r + 3) * PS2] = pack2(y1h[4 * r + 3], h3);
            }
        }
    } else if (jp < ch) {
#pragma unroll
        for (int dn = 0; dn < 2; dn++) {
            kA_scalar<RI, CI, TZ>(z, yh, yp, b, n + dn, 2 * jp, 2 * jp + 4);
            kA_scalar<RI, CI, TZ>(z, yh, yp, b, n + dn, 2 * jp + 1, 2 * jp + 5);
        }
    } else {
        int hp = jp - ch;
        int pc0 = (hp < 2) ? 2 * hp : (CI + 2 * hp);
#pragma unroll
        for (int dn = 0; dn < 2; dn++) {
#pragma unroll
            for (int s = 0; s < 2; s++) {
                int pc = pc0 + s;
                int jc = refl(pc - 4, CI);
                kA_scalar<RI, CI, TZ>(z, yh, yp, b, n + dn, jc, pc);
            }
        }
    }
}

// ===========================================================================
// kB: branch-free row upsampling, 2 rows per thread (R9 verbatim).
// ===========================================================================
template <int RO, int CO>
__global__ void __launch_bounds__(256)
kB(const uint2* __restrict__ yp, __half* __restrict__ Z) {
    constexpr int ch = CO / 4;
    constexpr int PS2 = (CO / 2 + 12) / 2;
    constexpr int LCH = ilog2c(ch);
    unsigned idx = blockIdx.x * 256u + threadIdx.x;
    int n = idx & (ch - 1);
    int rp = idx >> LCH;
    int row0 = 2 * rp;

#pragma unroll
    for (int rr = 0; rr < 2; rr++) {
        int row = row0 + rr;
        const uint2* q = yp + (size_t)row * PS2 + n;
        uint2 v0 = __ldg(q), v1 = __ldg(q + 1), v2 = __ldg(q + 2),
              v3 = __ldg(q + 3), v4 = __ldg(q + 4);
        float2 u0 = unpk_lo(v0), u1 = unpk_lo(v1), u2 = unpk_lo(v2),
               u3 = unpk_lo(v3), u4 = unpk_lo(v4);
        float2 w0 = unpk_hi(v0), w1 = unpk_hi(v1), w2 = unpk_hi(v2),
               w3 = unpk_hi(v3), w4 = unpk_hi(v4);
        float L[8], H[8];
        L[0] = u0.x; L[1] = u1.x; L[2] = u2.x; L[3] = u3.x;
        L[4] = u1.y; L[5] = u2.y; L[6] = u3.y; L[7] = u4.y;
        H[0] = w0.x; H[1] = w1.x; H[2] = w2.x; H[3] = w3.x;
        H[4] = w1.y; H[5] = w2.y; H[6] = w3.y; H[7] = w4.y;

        __half2 ha = __floats2half2_rn(LP0(L) + HP0(H), LP1(L) + HP1(H));
        __half2 hb = __floats2half2_rn(LP2(L) + HP2(H), LP3(L) + HP3(H));
        reinterpret_cast<uint2*>(Z + (size_t)row * CO)[n] = pack2(ha, hb);
    }
}

// ===========================================================================
// kC scalar path (R9 verbatim).
// ===========================================================================
template <int RI, int CI>
__device__ void kC_scalar(const __half* __restrict__ z, const float* __restrict__ yh,
                          uint2* __restrict__ yp, int b, int m, int jc, int pc) {
    constexpr int rh = RI / 2, PS2 = (CI + 10) / 2;
    int i0 = 2 * m;
    int pj = jc & 1;
    int o6[6];
    float s1v[6], s2v[6];
    int rr[6];
#pragma unroll
    for (int t = 0; t < 6; t++) {
        int rx = refl(i0 - 2 + t, RI);
        rr[t] = rx;
        int ii = rx >> 1, pi = rx & 1;
        o6[t] = ii * CI + (pi ^ pj);
        s1v[t] = (pi & pj) ? -1.f : 1.f;
        s2v[t] = (pi & (pj ^ 1)) ? -1.f : 1.f;
    }
    const __half* zb = z + (size_t)b * RI * CI + jc;
    const float* yb = yh + (size_t)b * 6 * rh * CI + 2 * (jc >> 1);
    const int sb = rh * CI;

    float zr[4];
#pragma unroll
    for (int t = 0; t < 4; t++) zr[t] = ld1(zb + rr[t + 1] * CI);

    float lr[6], hlr[6], hhr[6];
#pragma unroll
    for (int t = 0; t < 6; t++) {
        lr[t]  = s1v[t] * __ldg(yb + o6[t])          + s2v[t] * __ldg(yb + 5 * sb + o6[t]);
        hlr[t] = s1v[t] * __ldg(yb + 2 * sb + o6[t]) + s2v[t] * __ldg(yb + 3 * sb + o6[t]);
        hhr[t] = s1v[t] * __ldg(yb + 1 * sb + o6[t]) + s2v[t] * __ldg(yb + 4 * sb + o6[t]);
    }
    __half* o = (__half*)yp + (((size_t)b * RI + i0) * PS2 + (pc >> 1)) * 4 + (pc & 1);
    const int rs = PS2 * 4;
    o[0]      = __float2half(G0 * (zr[0] + zr[2]) + G1 * zr[1]
              + SH * (Q_E * (lr[0] + lr[4]) + Q_D * (lr[1] + lr[3]) + Q_F * lr[2]));
    o[rs]     = __float2half(G0 * (zr[1] + zr[3]) + G1 * zr[2]
              + SH * (Q_E * (lr[1] + lr[5]) + Q_D * (lr[2] + lr[4]) + Q_F * lr[3]));
    o[2]      = __float2half(SH * (G0 * (hlr[1] + hlr[3]) + G1 * hlr[2]
              + Q_E * (hhr[0] + hhr[4]) + Q_D * (hhr[1] + hhr[3]) + Q_F * hhr[2]));
    o[rs + 2] = __float2half(SH * (G0 * (hlr[2] + hlr[4]) + G1 * hlr[3]
              + Q_E * (hhr[1] + hhr[5]) + Q_D * (hhr[2] + hhr[4]) + Q_F * hhr[3]));
}

// ===========================================================================
// kC: final-level column filters, m-pair per thread (R9 verbatim).
// ===========================================================================
template <int RI, int CI>
__global__ void __launch_bounds__(256)
kC(const __half* __restrict__ z, const float* __restrict__ yh,
   uint2* __restrict__ yp) {
    constexpr int rh = RI / 2, chb = CI / 2, JP = chb + 5, PS2 = (CI + 10) / 2;
    constexpr int MP = rh / 2;
    unsigned idx = blockIdx.x * 256u + threadIdx.x;
    int jp = idx % JP;
    int mp = (idx / JP) % MP;
    int b = idx / (JP * MP);
    int mm = 2 * mp;

    if (jp < chb && mp >= 1 && mp <= MP - 2) {
        int i0 = 2 * mm;
        const __half2* z2 = (const __half2*)z + (size_t)b * RI * chb + jp;
        const float2* yb2 = (const float2*)yh + (size_t)b * 6 * rh * chb + jp;
        const int sstr = rh * chb;

        float2 zr[6];
#pragma unroll
        for (int t = 0; t < 6; t++) zr[t] = ld2(z2 + (i0 - 1 + t) * chb);

#define LOAD_PAIR4(S1, S2, B0, B1)                                            \
    {                                                                         \
        float2 w1[4], w2[4];                                                  \
        _Pragma("unroll") for (int t = 0; t < 4; t++) {                       \
            w1[t] = __ldg(yb2 + ((S1) * sstr + (mm - 1 + t) * chb));          \
            w2[t] = __ldg(yb2 + ((S2) * sstr + (mm - 1 + t) * chb));          \
        }                                                                     \
        _Pragma("unroll") for (int t = 0; t < 4; t++) {                       \
            B0[2 * t] = w1[t].x + w2[t].x;                                    \
            B1[2 * t] = w1[t].y + w2[t].y;                                    \
            B0[2 * t + 1] = w1[t].y - w2[t].y;                                \
            B1[2 * t + 1] = w2[t].x - w1[t].x;                                \
        }                                                                     \
    }
        float lr0[8], lr1[8], hl0[8], hl1[8], hh0[8], hh1[8];
        LOAD_PAIR4(0, 5, lr0, lr1);
        LOAD_PAIR4(2, 3, hl0, hl1);
        LOAD_PAIR4(1, 4, hh0, hh1);
#undef LOAD_PAIR4

        uint2* o = yp + ((size_t)b * RI + i0) * PS2 + (jp + 2);
#pragma unroll
        for (int q = 0; q < 4; q++) {
            __half2 h1 = __floats2half2_rn(
                G0 * (zr[q].x + zr[q + 2].x) + G1 * zr[q + 1].x
              + SH * (Q_E * (lr0[q] + lr0[q + 4]) + Q_D * (lr0[q + 1] + lr0[q + 3]) + Q_F * lr0[q + 2]),
                G0 * (zr[q].y + zr[q + 2].y) + G1 * zr[q + 1].y
              + SH * (Q_E * (lr1[q] + lr1[q + 4]) + Q_D * (lr1[q + 1] + lr1[q + 3]) + Q_F * lr1[q + 2]));
            __half2 h2 = __floats2half2_rn(
                SH * (G0 * (hl0[q + 1] + hl0[q + 3]) + G1 * hl0[q + 2]
              + Q_E * (hh0[q] + hh0[q + 4]) + Q_D * (hh0[q + 1] + hh0[q + 3]) + Q_F * hh0[q + 2]),
                SH * (G0 * (hl1[q + 1] + hl1[q + 3]) + G1 * hl1[q + 2]
              + Q_E * (hh1[q] + hh1[q + 4]) + Q_D * (hh1[q + 1] + hh1[q + 3]) + Q_F * hh1[q + 2]));
            o[q * PS2] = pack2(h1, h2);
        }
    } else if (jp < chb) {
#pragma unroll
        for (int dm = 0; dm < 2; dm++) {
            kC_scalar<RI, CI>(z, yh, yp, b, mm + dm, 2 * jp, 2 * jp + 4);
            kC_scalar<RI, CI>(z, yh, yp, b, mm + dm, 2 * jp + 1, 2 * jp + 5);
        }
    } else {
        int hp = jp - chb;
        int pc0 = (hp < 2) ? 2 * hp : (CI + 2 * hp);
#pragma unroll
        for (int dm = 0; dm < 2; dm++) {
#pragma unroll
            for (int s = 0; s < 2; s++) {
                int pc = pc0 + s;
                int jc = refl(pc - 4, CI);
                kC_scalar<RI, CI>(z, yh, yp, b, mm + dm, jc, pc);
            }
        }
    }
}

// ===========================================================================
// kD: branch-free final row filters, 2 rows per thread (R9 verbatim).
// ===========================================================================
template <int R, int C>
__global__ void __launch_bounds__(256)
kD(const uint2* __restrict__ yp, float* __restrict__ out) {
    constexpr int P = C / 4, PS2 = (C + 10) / 2;
    constexpr int LP = ilog2c(P);
    unsigned idx = blockIdx.x * 256u + threadIdx.x;
    int p = idx & (P - 1);
    int rp = idx >> LP;
    int row0 = 2 * rp;

#pragma unroll
    for (int rr = 0; rr < 2; rr++) {
        int row = row0 + rr;
        const uint2* q = yp + (size_t)row * PS2 + (2 * p + 1);
        uint2 v0 = __ldg(q), v1 = __ldg(q + 1), v2 = __ldg(q + 2), v3 = __ldg(q + 3);
        float2 f0 = unpk_lo(v0), f1 = unpk_lo(v1), f2 = unpk_lo(v2), f3 = unpk_lo(v3);
        float2 g0 = unpk_hi(v0), g1 = unpk_hi(v1), g2 = unpk_hi(v2), g3 = unpk_hi(v3);
        float a[6], v[8];
        a[0] = f0.y; a[1] = f1.x; a[2] = f1.y; a[3] = f2.x; a[4] = f2.y; a[5] = f3.x;
        v[0] = g0.x; v[1] = g0.y; v[2] = g1.x; v[3] = g1.y;
        v[4] = g2.x; v[5] = g2.y; v[6] = g3.x; v[7] = g3.y;
        float4 o;
        o.x = G0 * (a[0] + a[2]) + G1 * a[1] + Q_E * (v[0] + v[4]) + Q_D * (v[1] + v[3]) + Q_F * v[2];
        o.y = G0 * (a[1] + a[3]) + G1 * a[2] + Q_E * (v[1] + v[5]) + Q_D * (v[2] + v[4]) + Q_F * v[3];
        o.z = G0 * (a[2] + a[4]) + G1 * a[3] + Q_E * (v[2] + v[6]) + Q_D * (v[3] + v[5]) + Q_F * v[4];
        o.w = G0 * (a[3] + a[5]) + G1 * a[4] + Q_E * (v[3] + v[7]) + Q_D * (v[4] + v[6]) + Q_F * v[5];
        reinterpret_cast<float4*>(out + (size_t)row * C)[p] = o;
    }
}

extern "C" void kernel_launch(void* const* d_in, const int* in_sizes, int n_in,
                              void* d_out, int out_size) {
    const float *yl = nullptr, *yh0 = nullptr, *yh1 = nullptr, *yh2 = nullptr;
    for (int i = 0; i < n_in; i++) {
        switch (in_sizes[i]) {
            case 524288:   yl  = (const float*)d_in[i]; break;  // 128*64*64
            case 25165824: yh0 = (const float*)d_in[i]; break;  // 128*6*128*128*2
            case 6291456:  yh1 = (const float*)d_in[i]; break;  // 128*6*64*64*2
            case 1572864:  yh2 = (const float*)d_in[i]; break;  // 128*6*32*32*2
            default: break;
        }
    }

    uint2* pyp;
    __half *pz128, *pz256;
    cudaGetSymbolAddress((void**)&pyp,   g_yp);
    cudaGetSymbolAddress((void**)&pz128, g_z128);
    cudaGetSymbolAddress((void**)&pz256, g_z256);

    // Level 1: (64,64) -> (128,128).  kA threads: 128 * 16 * 37
    kA<64, 64, float><<<128 * 16 * 37 / 256, 256>>>(yl, yh2, pyp);
    kB<128, 128><<<128 * 64 * 32 / 256, 256>>>(pyp, pz128);

    // Level 2: (128,128) -> (256,256). kA threads: 128 * 32 * 69
    kA<128, 128, __half><<<128 * 32 * 69 / 256, 256>>>(pz128, yh1, pyp);
    kB<256, 256><<<128 * 128 * 64 / 256, 256>>>(pyp, pz256);

    // Final level
    kC<256, 256><<<128 * 64 * 133 / 256, 256>>>(pz256, yh0, pyp);
    kD<256, 256><<<128 * 128 * 64 / 256, 256>>>(pyp, (float*)d_out);
}

// round 15
// speedup vs baseline: 1.2607x; 1.0088x over previous
#include <cuda_runtime.h>
#include <cuda_fp16.h>

// ---------------------------------------------------------------------------
// Inverse DTCWT, 3 levels. Split kernels, fp16 intermediates, interleaved
// padded y buffer. R14 kA (n-pair) + R15 kC (m-QUAD, two-pass).
// ---------------------------------------------------------------------------

#define SH   0.70710678118654752440f
#define C_A  0.23389032f
#define C_B  0.5875183f
#define C_C  0.11430184f
#define C_D  0.76027237f
#define C_E  0.08832942f
#define C_F  0.03516384f

#define G0   0.35355339059327f
#define G1   0.70710678118655f
#define Q_E  (-0.08838834764832f)
#define Q_D  (-0.17677669529664f)
#define Q_F  0.53033008588991f

#define LP0(L) ( C_A*L[1] + C_B*L[2] - C_C*L[3])
#define LP1(L) ( C_D*L[5] - C_E*L[6] + C_F*L[7])
#define LP2(L) ( C_F*L[0] - C_E*L[1] + C_D*L[2])
#define LP3(L) (-C_C*L[4] + C_B*L[5] + C_A*L[6])
#define HP0(H) (-C_D*H[5] + C_E*H[6] - C_F*H[7])
#define HP1(H) ( C_A*H[1] + C_B*H[2] - C_C*H[3])
#define HP2(H) (-C_C*H[4] + C_B*H[5] + C_A*H[6])
#define HP3(H) (-C_F*H[0] + C_E*H[1] - C_D*H[2])

__device__ uint2  g_yp[128 * 256 * 134];
__device__ __half g_z128[128 * 128 * 128];
__device__ __half g_z256[128 * 256 * 256];

__device__ __forceinline__ int refl(int i, int n) {
    i = (i < 0) ? (-1 - i) : i;
    return (i >= n) ? (2 * n - 1 - i) : i;
}

__host__ __device__ constexpr int ilog2c(int v) { return v <= 1 ? 0 : 1 + ilog2c(v >> 1); }

__device__ __forceinline__ float  ld1(const float* p)   { return __ldg(p); }
__device__ __forceinline__ float  ld1(const __half* p)  { return __half2float(__ldg(p)); }
__device__ __forceinline__ float2 ld2(const float2* p)  { return __ldg(p); }
__device__ __forceinline__ float2 ld2(const __half2* p) { return __half22float2(__ldg(p)); }

__device__ __forceinline__ uint2 pack2(__half2 a, __half2 b) {
    uint2 r;
    r.x = *reinterpret_cast<const unsigned*>(&a);
    r.y = *reinterpret_cast<const unsigned*>(&b);
    return r;
}
__device__ __forceinline__ float2 unpk_lo(uint2 v) {
    __half2 h = *reinterpret_cast<const __half2*>(&v.x);
    return __half22float2(h);
}
__device__ __forceinline__ float2 unpk_hi(uint2 v) {
    __half2 h = *reinterpret_cast<const __half2*>(&v.y);
    return __half22float2(h);
}

template <typename T> struct vec2of;
template <> struct vec2of<float>  { using t = float2; };
template <> struct vec2of<__half> { using t = __half2; };

// ===========================================================================
// kA scalar path (single n, single col).
// ===========================================================================
template <int RI, int CI, typename TZ>
__device__ void kA_scalar(const TZ* __restrict__ z, const float* __restrict__ yh,
                          uint2* __restrict__ yp, int b, int n, int jc, int pc) {
    constexpr int rh = RI / 2, PS2 = (CI + 12) / 2;
    const int d8[8] = {-4, -2, 0, 2, -1, 1, 3, 5};
    int pj = jc & 1;
    int rw[8], oB[8];
    float s1v[8], s2v[8];
#pragma unroll
    for (int t = 0; t < 8; t++) {
        int rr = refl(2 * n + d8[t], RI);
        rw[t] = rr;
        int ii = rr >> 1, pi = rr & 1;
        oB[t] = ii * CI + (pi ^ pj);
        s1v[t] = (pi & pj) ? -1.f : 1.f;
        s2v[t] = (pi & (pj ^ 1)) ? -1.f : 1.f;
    }
    const TZ* zb = z + (size_t)b * RI * CI + jc;
    const float* yb = yh + (size_t)b * 6 * rh * CI + 2 * (jc >> 1);
    const int sb = rh * CI;

    float L[8], H[8], A[8], B[8];
#pragma unroll
    for (int t = 0; t < 8; t++) L[t] = ld1(zb + rw[t] * CI);
#pragma unroll
    for (int t = 0; t < 8; t++) {
        H[t] = s1v[t] * __ldg(yb + oB[t]) + s2v[t] * __ldg(yb + 5 * sb + oB[t]);
        A[t] = s1v[t] * __ldg(yb + 2 * sb + oB[t]) + s2v[t] * __ldg(yb + 3 * sb + oB[t]);
        B[t] = s1v[t] * __ldg(yb + 1 * sb + oB[t]) + s2v[t] * __ldg(yb + 4 * sb + oB[t]);
    }

    __half* o = (__half*)yp + (((size_t)b * 2 * RI + 4 * n) * PS2 + (pc >> 1)) * 4 + (pc & 1);
    const int rs = PS2 * 4;
    o[0]          = __float2half(LP0(L) + SH * HP0(H));
    o[2]          = __float2half(SH * (LP0(A) + HP0(B)));
    o[rs]         = __float2half(LP1(L) + SH * HP1(H));
    o[rs + 2]     = __float2half(SH * (LP1(A) + HP1(B)));
    o[2 * rs]     = __float2half(LP2(L) + SH * HP2(H));
    o[2 * rs + 2] = __float2half(SH * (LP2(A) + HP2(B)));
    o[3 * rs]     = __float2half(LP3(L) + SH * HP3(H));
    o[3 * rs + 2] = __float2half(SH * (LP3(A) + HP3(B)));
}

// ===========================================================================
// kA: column upsampling, n-PAIR per thread (R14 verbatim).
// ===========================================================================
template <int RI, int CI, typename TZ>
__global__ void __launch_bounds__(256)
kA(const TZ* __restrict__ z, const float* __restrict__ yh,
   uint2* __restrict__ yp) {
    constexpr int rh = RI / 2, ch = CI / 2, JP = ch + 5, PS2 = (CI + 12) / 2;
    constexpr int NPH = rh / 2;
    using TZ2 = typename vec2of<TZ>::t;
    unsigned idx = blockIdx.x * 256u + threadIdx.x;
    int jp = idx % JP;
    int np = (idx / JP) % NPH;
    int b = idx / (JP * NPH);
    int n = 2 * np;

    if (jp < ch && np >= 1 && np <= NPH - 2) {
        const TZ2* z2 = (const TZ2*)z + (size_t)b * RI * ch + jp;
        const float2* yb2 = (const float2*)yh + (size_t)b * 6 * rh * ch + jp;
        const int sstr = rh * ch;
        int base = 2 * n;

        __half2 y1h[8];
        {
            float2 ze[5], zo[5];
#pragma unroll
            for (int t = 0; t < 5; t++) {
                ze[t] = ld2(z2 + (base - 4 + 2 * t) * ch);
                zo[t] = ld2(z2 + (base - 1 + 2 * t) * ch);
            }
            float E0[5], E1[5], O0[5], O1[5];
            {
                float2 w1[6], w2[6];
#pragma unroll
                for (int t = 0; t < 6; t++) {
                    w1[t] = __ldg(yb2 + (0 * sstr + (n - 2 + t) * ch));
                    w2[t] = __ldg(yb2 + (5 * sstr + (n - 2 + t) * ch));
                }
#pragma unroll
                for (int t = 0; t < 5; t++) {
                    E0[t] = w1[t].x + w2[t].x;
                    E1[t] = w1[t].y + w2[t].y;
                    O0[t] = w1[t + 1].y - w2[t + 1].y;
                    O1[t] = w2[t + 1].x - w1[t + 1].x;
                }
            }
#pragma unroll
            for (int r = 0; r < 2; r++) {
                float L0[8], L1[8], H0[8], H1[8];
#pragma unroll
                for (int t = 0; t < 4; t++) {
                    L0[t] = ze[r + t].x; L1[t] = ze[r + t].y;
                    L0[4 + t] = zo[r + t].x; L1[4 + t] = zo[r + t].y;
                    H0[t] = E0[r + t]; H1[t] = E1[r + t];
                    H0[4 + t] = O0[r + t]; H1[4 + t] = O1[r + t];
                }
                y1h[4 * r + 0] = __floats2half2_rn(LP0(L0) + SH * HP0(H0), LP0(L1) + SH * HP0(H1));
                y1h[4 * r + 1] = __floats2half2_rn(LP1(L0) + SH * HP1(H0), LP1(L1) + SH * HP1(H1));
                y1h[4 * r + 2] = __floats2half2_rn(LP2(L0) + SH * HP2(H0), LP2(L1) + SH * HP2(H1));
                y1h[4 * r + 3] = __floats2half2_rn(LP3(L0) + SH * HP3(H0), LP3(L1) + SH * HP3(H1));
            }
        }

        uint2* o = yp + ((size_t)b * 2 * RI + 4 * n) * PS2 + (jp + 2);
        {
            float AE0[5], AE1[5], AO0[5], AO1[5];
            float BE0[5], BE1[5], BO0[5], BO1[5];
            {
                float2 w1[6], w2[6];
#pragma unroll
                for (int t = 0; t < 6; t++) {
                    w1[t] = __ldg(yb2 + (2 * sstr + (n - 2 + t) * ch));
                    w2[t] = __ldg(yb2 + (3 * sstr + (n - 2 + t) * ch));
                }
#pragma unroll
                for (int t = 0; t < 5; t++) {
                    AE0[t] = w1[t].x + w2[t].x;
                    AE1[t] = w1[t].y + w2[t].y;
                    AO0[t] = w1[t + 1].y - w2[t + 1].y;
                    AO1[t] = w2[t + 1].x - w1[t + 1].x;
                }
            }
            {
                float2 w1[6], w2[6];
#pragma unroll
                for (int t = 0; t < 6; t++) {
                    w1[t] = __ldg(yb2 + (1 * sstr + (n - 2 + t) * ch));
                    w2[t] = __ldg(yb2 + (4 * sstr + (n - 2 + t) * ch));
                }
#pragma unroll
                for (int t = 0; t < 5; t++) {
                    BE0[t] = w1[t].x + w2[t].x;
                    BE1[t] = w1[t].y + w2[t].y;
                    BO0[t] = w1[t + 1].y - w2[t + 1].y;
                    BO1[t] = w2[t + 1].x - w1[t + 1].x;
                }
            }
#pragma unroll
            for (int r = 0; r < 2; r++) {
                float A0[8], A1[8], B0[8], B1[8];
#pragma unroll
                for (int t = 0; t < 4; t++) {
                    A0[t] = AE0[r + t]; A1[t] = AE1[r + t];
                    A0[4 + t] = AO0[r + t]; A1[4 + t] = AO1[r + t];
                    B0[t] = BE0[r + t]; B1[t] = BE1[r + t];
                    B0[4 + t] = BO0[r + t]; B1[4 + t] = BO1[r + t];
                }
                __half2 h0 = __floats2half2_rn(SH * (LP0(A0) + HP0(B0)), SH * (LP0(A1) + HP0(B1)));
                __half2 h1 = __floats2half2_rn(SH * (LP1(A0) + HP1(B0)), SH * (LP1(A1) + HP1(B1)));
                __half2 h2 = __floats2half2_rn(SH * (LP2(A0) + HP2(B0)), SH * (LP2(A1) + HP2(B1)));
                __half2 h3 = __floats2half2_rn(SH * (LP3(A0) + HP3(B0)), SH * (LP3(A1) + HP3(B1)));
                o[(4 * r + 0) * PS2] = pack2(y1h[4 * r + 0], h0);
                o[(4 * r + 1) * PS2] = pack2(y1h[4 * r + 1], h1);
                o[(4 * r + 2) * PS2] = pack2(y1h[4 * r + 2], h2);
                o[(4 * r + 3) * PS2] = pack2(y1h[4 * r + 3], h3);
            }
        }
    } else if (jp < ch) {
#pragma unroll
        for (int dn = 0; dn < 2; dn++) {
            kA_scalar<RI, CI, TZ>(z, yh, yp, b, n + dn, 2 * jp, 2 * jp + 4);
            kA_scalar<RI, CI, TZ>(z, yh, yp, b, n + dn, 2 * jp + 1, 2 * jp + 5);
        }
    } else {
        int hp = jp - ch;
        int pc0 = (hp < 2) ? 2 * hp : (CI + 2 * hp);
#pragma unroll
        for (int dn = 0; dn < 2; dn++) {
#pragma unroll
            for (int s = 0; s < 2; s++) {
                int pc = pc0 + s;
                int jc = refl(pc - 4, CI);
                kA_scalar<RI, CI, TZ>(z, yh, yp, b, n + dn, jc, pc);
            }
        }
    }
}

// ===========================================================================
// kB: branch-free row upsampling, 2 rows per thread (R9 verbatim).
// ===========================================================================
template <int RO, int CO>
__global__ void __launch_bounds__(256)
kB(const uint2* __restrict__ yp, __half* __restrict__ Z) {
    constexpr int ch = CO / 4;
    constexpr int PS2 = (CO / 2 + 12) / 2;
    constexpr int LCH = ilog2c(ch);
    unsigned idx = blockIdx.x * 256u + threadIdx.x;
    int n = idx & (ch - 1);
    int rp = idx >> LCH;
    int row0 = 2 * rp;

#pragma unroll
    for (int rr = 0; rr < 2; rr++) {
        int row = row0 + rr;
        const uint2* q = yp + (size_t)row * PS2 + n;
        uint2 v0 = __ldg(q), v1 = __ldg(q + 1), v2 = __ldg(q + 2),
              v3 = __ldg(q + 3), v4 = __ldg(q + 4);
        float2 u0 = unpk_lo(v0), u1 = unpk_lo(v1), u2 = unpk_lo(v2),
               u3 = unpk_lo(v3), u4 = unpk_lo(v4);
        float2 w0 = unpk_hi(v0), w1 = unpk_hi(v1), w2 = unpk_hi(v2),
               w3 = unpk_hi(v3), w4 = unpk_hi(v4);
        float L[8], H[8];
        L[0] = u0.x; L[1] = u1.x; L[2] = u2.x; L[3] = u3.x;
        L[4] = u1.y; L[5] = u2.y; L[6] = u3.y; L[7] = u4.y;
        H[0] = w0.x; H[1] = w1.x; H[2] = w2.x; H[3] = w3.x;
        H[4] = w1.y; H[5] = w2.y; H[6] = w3.y; H[7] = w4.y;

        __half2 ha = __floats2half2_rn(LP0(L) + HP0(H), LP1(L) + HP1(H));
        __half2 hb = __floats2half2_rn(LP2(L) + HP2(H), LP3(L) + HP3(H));
        reinterpret_cast<uint2*>(Z + (size_t)row * CO)[n] = pack2(ha, hb);
    }
}

// ===========================================================================
// kC scalar path (single m).
// ===========================================================================
template <int RI, int CI>
__device__ void kC_scalar(const __half* __restrict__ z, const float* __restrict__ yh,
                          uint2* __restrict__ yp, int b, int m, int jc, int pc) {
    constexpr int rh = RI / 2, PS2 = (CI + 10) / 2;
    int i0 = 2 * m;
    int pj = jc & 1;
    int o6[6];
    float s1v[6], s2v[6];
    int rr[6];
#pragma unroll
    for (int t = 0; t < 6; t++) {
        int rx = refl(i0 - 2 + t, RI);
        rr[t] = rx;
        int ii = rx >> 1, pi = rx & 1;
        o6[t] = ii * CI + (pi ^ pj);
        s1v[t] = (pi & pj) ? -1.f : 1.f;
        s2v[t] = (pi & (pj ^ 1)) ? -1.f : 1.f;
    }
    const __half* zb = z + (size_t)b * RI * CI + jc;
    const float* yb = yh + (size_t)b * 6 * rh * CI + 2 * (jc >> 1);
    const int sb = rh * CI;

    float zr[4];
#pragma unroll
    for (int t = 0; t < 4; t++) zr[t] = ld1(zb + rr[t + 1] * CI);

    float lr[6], hlr[6], hhr[6];
#pragma unroll
    for (int t = 0; t < 6; t++) {
        lr[t]  = s1v[t] * __ldg(yb + o6[t])          + s2v[t] * __ldg(yb + 5 * sb + o6[t]);
        hlr[t] = s1v[t] * __ldg(yb + 2 * sb + o6[t]) + s2v[t] * __ldg(yb + 3 * sb + o6[t]);
        hhr[t] = s1v[t] * __ldg(yb + 1 * sb + o6[t]) + s2v[t] * __ldg(yb + 4 * sb + o6[t]);
    }
    __half* o = (__half*)yp + (((size_t)b * RI + i0) * PS2 + (pc >> 1)) * 4 + (pc & 1);
    const int rs = PS2 * 4;
    o[0]      = __float2half(G0 * (zr[0] + zr[2]) + G1 * zr[1]
              + SH * (Q_E * (lr[0] + lr[4]) + Q_D * (lr[1] + lr[3]) + Q_F * lr[2]));
    o[rs]     = __float2half(G0 * (zr[1] + zr[3]) + G1 * zr[2]
              + SH * (Q_E * (lr[1] + lr[5]) + Q_D * (lr[2] + lr[4]) + Q_F * lr[3]));
    o[2]      = __float2half(SH * (G0 * (hlr[1] + hlr[3]) + G1 * hlr[2]
              + Q_E * (hhr[0] + hhr[4]) + Q_D * (hhr[1] + hhr[3]) + Q_F * hhr[2]));
    o[rs + 2] = __float2half(SH * (G0 * (hlr[2] + hlr[4]) + G1 * hlr[3]
              + Q_E * (hhr[1] + hhr[5]) + Q_D * (hhr[2] + hhr[4]) + Q_F * hhr[3]));
}

// ===========================================================================
// kC: final-level column filters, m-QUAD per thread (8 output rows),
// two-pass (y1 banked as half2, then hl/hh).
// Band slots 0..11 from subband rows mm-1..mm+4 (6 rows per pair).
// ===========================================================================
template <int RI, int CI>
__global__ void __launch_bounds__(256)
kC(const __half* __restrict__ z, const float* __restrict__ yh,
   uint2* __restrict__ yp) {
    constexpr int rh = RI / 2, chb = CI / 2, JP = chb + 5, PS2 = (CI + 10) / 2;
    constexpr int MQ = rh / 4;
    unsigned idx = blockIdx.x * 256u + threadIdx.x;
    int jp = idx % JP;
    int mq = (idx / JP) % MQ;
    int b = idx / (JP * MQ);
    int mm = 4 * mq;
    int i0 = 2 * mm;

    if (jp < chb && mq >= 1 && mq <= MQ - 2) {
        const __half2* z2 = (const __half2*)z + (size_t)b * RI * chb + jp;
        const float2* yb2 = (const float2*)yh + (size_t)b * 6 * rh * chb + jp;
        const int sstr = rh * chb;

#define LOAD_PAIR6(S1, S2, B0, B1)                                            \
    {                                                                         \
        float2 w1[6], w2[6];                                                  \
        _Pragma("unroll") for (int t = 0; t < 6; t++) {                       \
            w1[t] = __ldg(yb2 + ((S1) * sstr + (mm - 1 + t) * chb));          \
            w2[t] = __ldg(yb2 + ((S2) * sstr + (mm - 1 + t) * chb));          \
        }                                                                     \
        _Pragma("unroll") for (int t = 0; t < 6; t++) {                       \
            B0[2 * t] = w1[t].x + w2[t].x;                                    \
            B1[2 * t] = w1[t].y + w2[t].y;                                    \
            B0[2 * t + 1] = w1[t].y - w2[t].y;                                \
            B1[2 * t + 1] = w2[t].x - w1[t].x;                                \
        }                                                                     \
    }

        __half2 y1h[8];
        // ---- pass 1: y1 = colfilter(z,g0o) + colfilter(lh,g1o) ----
        {
            float2 zr[10];
#pragma unroll
            for (int t = 0; t < 10; t++) zr[t] = ld2(z2 + (i0 - 1 + t) * chb);
            float lr0[12], lr1[12];
            LOAD_PAIR6(0, 5, lr0, lr1);
#pragma unroll
            for (int q = 0; q < 8; q++) {
                y1h[q] = __floats2half2_rn(
                    G0 * (zr[q].x + zr[q + 2].x) + G1 * zr[q + 1].x
                  + SH * (Q_E * (lr0[q] + lr0[q + 4]) + Q_D * (lr0[q + 1] + lr0[q + 3]) + Q_F * lr0[q + 2]),
                    G0 * (zr[q].y + zr[q + 2].y) + G1 * zr[q + 1].y
                  + SH * (Q_E * (lr1[q] + lr1[q + 4]) + Q_D * (lr1[q + 1] + lr1[q + 3]) + Q_F * lr1[q + 2]));
            }
        }
        // ---- pass 2: y2 = colfilter(hl,g0o) + colfilter(hh,g1o) ----
        {
            float hl0[12], hl1[12], hh0[12], hh1[12];
            LOAD_PAIR6(2, 3, hl0, hl1);
            LOAD_PAIR6(1, 4, hh0, hh1);
            uint2* o = yp + ((size_t)b * RI + i0) * PS2 + (jp + 2);
#pragma unroll
            for (int q = 0; q < 8; q++) {
                __half2 h2 = __floats2half2_rn(
                    SH * (G0 * (hl0[q + 1] + hl0[q + 3]) + G1 * hl0[q + 2]
                  + Q_E * (hh0[q] + hh0[q + 4]) + Q_D * (hh0[q + 1] + hh0[q + 3]) + Q_F * hh0[q + 2]),
                    SH * (G0 * (hl1[q + 1] + hl1[q + 3]) + G1 * hl1[q + 2]
                  + Q_E * (hh1[q] + hh1[q + 4]) + Q_D * (hh1[q + 1] + hh1[q + 3]) + Q_F * hh1[q + 2]));
                o[q * PS2] = pack2(y1h[q], h2);
            }
        }
#undef LOAD_PAIR6
    } else if (jp < chb) {
#pragma unroll
        for (int dm = 0; dm < 4; dm++) {
            kC_scalar<RI, CI>(z, yh, yp, b, mm + dm, 2 * jp, 2 * jp + 4);
            kC_scalar<RI, CI>(z, yh, yp, b, mm + dm, 2 * jp + 1, 2 * jp + 5);
        }
    } else {
        int hp = jp - chb;
        int pc0 = (hp < 2) ? 2 * hp : (CI + 2 * hp);
#pragma unroll
        for (int dm = 0; dm < 4; dm++) {
#pragma unroll
            for (int s = 0; s < 2; s++) {
                int pc = pc0 + s;
                int jc = refl(pc - 4, CI);
                kC_scalar<RI, CI>(z, yh, yp, b, mm + dm, jc, pc);
            }
        }
    }
}

// ===========================================================================
// kD: branch-free final row filters, 2 rows per thread (R9 verbatim).
// ===========================================================================
template <int R, int C>
__global__ void __launch_bounds__(256)
kD(const uint2* __restrict__ yp, float* __restrict__ out) {
    constexpr int P = C / 4, PS2 = (C + 10) / 2;
    constexpr int LP = ilog2c(P);
    unsigned idx = blockIdx.x * 256u + threadIdx.x;
    int p = idx & (P - 1);
    int rp = idx >> LP;
    int row0 = 2 * rp;

#pragma unroll
    for (int rr = 0; rr < 2; rr++) {
        int row = row0 + rr;
        const uint2* q = yp + (size_t)row * PS2 + (2 * p + 1);
        uint2 v0 = __ldg(q), v1 = __ldg(q + 1), v2 = __ldg(q + 2), v3 = __ldg(q + 3);
        float2 f0 = unpk_lo(v0), f1 = unpk_lo(v1), f2 = unpk_lo(v2), f3 = unpk_lo(v3);
        float2 g0 = unpk_hi(v0), g1 = unpk_hi(v1), g2 = unpk_hi(v2), g3 = unpk_hi(v3);
        float a[6], v[8];
        a[0] = f0.y; a[1] = f1.x; a[2] = f1.y; a[3] = f2.x; a[4] = f2.y; a[5] = f3.x;
        v[0] = g0.x; v[1] = g0.y; v[2] = g1.x; v[3] = g1.y;
        v[4] = g2.x; v[5] = g2.y; v[6] = g3.x; v[7] = g3.y;
        float4 o;
        o.x = G0 * (a[0] + a[2]) + G1 * a[1] + Q_E * (v[0] + v[4]) + Q_D * (v[1] + v[3]) + Q_F * v[2];
        o.y = G0 * (a[1] + a[3]) + G1 * a[2] + Q_E * (v[1] + v[5]) + Q_D * (v[2] + v[4]) + Q_F * v[3];
        o.z = G0 * (a[2] + a[4]) + G1 * a[3] + Q_E * (v[2] + v[6]) + Q_D * (v[3] + v[5]) + Q_F * v[4];
        o.w = G0 * (a[3] + a[5]) + G1 * a[4] + Q_E * (v[3] + v[7]) + Q_D * (v[4] + v[6]) + Q_F * v[5];
        reinterpret_cast<float4*>(out + (size_t)row * C)[p] = o;
    }
}

extern "C" void kernel_launch(void* const* d_in, const int* in_sizes, int n_in,
                              void* d_out, int out_size) {
    const float *yl = nullptr, *yh0 = nullptr, *yh1 = nullptr, *yh2 = nullptr;
    for (int i = 0; i < n_in; i++) {
        switch (in_sizes[i]) {
            case 524288:   yl  = (const float*)d_in[i]; break;  // 128*64*64
            case 25165824: yh0 = (const float*)d_in[i]; break;  // 128*6*128*128*2
            case 6291456:  yh1 = (const float*)d_in[i]; break;  // 128*6*64*64*2
            case 1572864:  yh2 = (const float*)d_in[i]; break;  // 128*6*32*32*2
            default: break;
        }
    }

    uint2* pyp;
    __half *pz128, *pz256;
    cudaGetSymbolAddress((void**)&pyp,   g_yp);
    cudaGetSymbolAddress((void**)&pz128, g_z128);
    cudaGetSymbolAddress((void**)&pz256, g_z256);

    // Level 1: (64,64) -> (128,128)
    kA<64, 64, float><<<128 * 16 * 37 / 256, 256>>>(yl, yh2, pyp);
    kB<128, 128><<<128 * 64 * 32 / 256, 256>>>(pyp, pz128);

    // Level 2: (128,128) -> (256,256)
    kA<128, 128, __half><<<128 * 32 * 69 / 256, 256>>>(pz128, yh1, pyp);
    kB<256, 256><<<128 * 128 * 64 / 256, 256>>>(pyp, pz256);

    // Final level: kC threads = 128 * (rh/4=32) * 133
    kC<256, 256><<<128 * 32 * 133 / 256, 256>>>(pz256, yh0, pyp);
    kD<256, 256><<<128 * 128 * 64 / 256, 256>>>(pyp, (float*)d_out);
}